// round 13
// baseline (speedup 1.0000x reference)
#include <cuda_runtime.h>
#include <cuda_bf16.h>
#include <math.h>
#include <stdint.h>

#define BB 32
#define HH 512
#define VOCAB 50257
#define VPAD  50432          // multiple of 256
#define NB8   (VPAD/8)       // 6304 fragment columns
#define NBLK  (VPAD/256)     // 197 big-gemm blocks (256 cols each)
#define NBP   208            // padded partial stride
#define NF4   12565          // float4 groups covering VOCAB

// ---------------- device scratch ----------------
__device__ float g_xcur[BB * HH];              // t=0 start embeddings only
__device__ float g_h0s[2][BB * HH];
__device__ float g_h1s[2][BB * HH];
__device__ float g_e0[BB * HH];                // exp(logits0)
__device__ float g_ps0[BB * 128];              // layer-0 partial row sums per block
__device__ uint4 g_Af[2 * 32 * 2 * 32];        // [hl][ks][m][lane] A fragments for k_big
__device__ uint4 g_Bf[(long)32 * NB8 * 32];    // [ks][n8][lane] -> {bh0,bh1,bl0,bl1}
__device__ float g_c1p[VPAD];
__device__ float g_E[BB * VPAD];               // exp(logits1)
__device__ float g_psum[BB * NBP];
__device__ float g_pmax[BB * NBP];
__device__ int   g_pidx[BB * NBP];
__device__ float g_invS[BB];                   // final step only

// ---------------- helpers ----------------
__device__ __forceinline__ uint32_t pk_bf2(float a, float b) {
    uint32_t ua = (uint32_t)__bfloat16_as_ushort(__float2bfloat16_rn(a));
    uint32_t ub = (uint32_t)__bfloat16_as_ushort(__float2bfloat16_rn(b));
    return ua | (ub << 16);
}
__device__ __forceinline__ float bf_hi(float v) {
    return __bfloat162float(__float2bfloat16_rn(v));
}
__device__ __forceinline__ void mma_bf16(float* d, const uint4& a, uint32_t b0, uint32_t b1) {
    asm volatile(
        "mma.sync.aligned.m16n8k16.row.col.f32.bf16.bf16.f32 "
        "{%0,%1,%2,%3},{%4,%5,%6,%7},{%8,%9},{%0,%1,%2,%3};\n"
        : "+f"(d[0]), "+f"(d[1]), "+f"(d[2]), "+f"(d[3])
        : "r"(a.x), "r"(a.y), "r"(a.z), "r"(a.w), "r"(b0), "r"(b1));
}

// ---------------- one-time kernels ----------------
__global__ void k_init(const int* __restrict__ x, const float* __restrict__ h_prev,
                       const float* __restrict__ emb) {
    int b = blockIdx.x, j = threadIdx.x;
    g_xcur[b * HH + j]   = emb[(long)x[b] * HH + j];
    g_h0s[0][b * HH + j] = h_prev[b * HH + j];
    g_h1s[0][b * HH + j] = h_prev[b * HH + j];
}

__global__ void k_pack_c1(const float* __restrict__ c1) {
    int i = blockIdx.x * blockDim.x + threadIdx.x;
    if (i < VPAD) g_c1p[i] = (i < VOCAB) ? c1[i] : -1e30f;
}

__global__ void k_pack_b(const float* __restrict__ V1) {
    __shared__ float sv[16][257];
    int bx = blockIdx.x, ks = blockIdx.y, tid = threadIdx.x;
    int cbase = bx * 256;
    #pragma unroll
    for (int r = 0; r < 16; r++) {
        int col = cbase + tid;
        int k = ks * 16 + r;
        sv[r][tid] = (col < VOCAB) ? V1[(long)k * VOCAB + col] : 0.0f;
    }
    __syncthreads();
    for (int e = tid; e < 1024; e += 256) {
        int lane = e & 31, n8l = e >> 5;
        int colL = n8l * 8 + (lane >> 2);
        int rr = (lane & 3) * 2;
        float v0 = sv[rr][colL],     v1 = sv[rr + 1][colL];
        float v8 = sv[rr + 8][colL], v9 = sv[rr + 9][colL];
        float h0 = bf_hi(v0), h1 = bf_hi(v1), h8 = bf_hi(v8), h9 = bf_hi(v9);
        uint4 o;
        o.x = pk_bf2(h0, h1);
        o.y = pk_bf2(h8, h9);
        o.z = pk_bf2(v0 - h0, v1 - h1);
        o.w = pk_bf2(v8 - h8, v9 - h9);
        g_Bf[((long)ks * NB8 + bx * 32 + n8l) * 32 + lane] = o;
    }
}

// ---------------- small GEMM: full staging, 512 threads, 4-way split-K ----------------
// MODE 0: cell0  per-block comb (argmax+invS) -> stage x=emb[am];
//                h0n = tanh(x@U0 + h0@W0 + b0) + y(t-1) first half
// MODE 1: head0  per-block invS; e0 = exp(h0n@V0 + c0), partials + y(t-1) second half
// MODE 2: cell1  inv from ps0; x1 = tanh(e0*inv) staged inline;
//                h1n = tanh(x1@U1 + h1@W1 + b1) + out_h + frag pack
template<int MODE>
__global__ void __launch_bounds__(512) k_cellx(
        const float* __restrict__ A1, const float* __restrict__ A2,
        const float* __restrict__ W1, const float* __restrict__ W2,
        const float* __restrict__ bias, float* __restrict__ outp,
        float* __restrict__ out_h, float* __restrict__ out_y,
        const float* __restrict__ emb,
        int t, int tprev, int T) {
    constexpr bool DUAL = (MODE != 1);
    extern __shared__ float sm[];
    float* sA1 = sm;                                   // 32 x 516
    float* sA2 = DUAL ? (sm + 16512) : nullptr;        // 32 x 516
    float* sW1 = sm + (DUAL ? 33024 : 16512);          // 4 x 516
    float* sW2 = DUAL ? (sW1 + 2064) : nullptr;        // 4 x 516
    float* sRed = sW1 + (DUAL ? 4128 : 2064);          // 512
    float* sH   = sRed + 512;                          // 32 x 5
    float* sInv = sH + 160;                            // 32 (MODE 2 softmax0 inv)
    float* sIS  = sInv + 32;                           // 32 (vocab-softmax invS)
    int*   sAm  = (int*)(sIS + 32);                    // 32 (argmax token ids)

    int tid = threadIdx.x;
    int bx = blockIdx.x;
    int jb = bx * 4;
    int quarter = tid >> 7;
    int sub  = tid & 127;
    int jl = sub & 3, r = sub >> 2;

    // ---- per-block comb: argmax (MODE 0) and/or invS (MODE 0/1) from k_big(t-1) ----
    if (MODE == 0 && tprev >= 0) {
        int row = tid >> 4, l16 = tid & 15;
        float s = 0.f, mv = -3e38f; int mi = 0;
        for (int i = l16; i < NBLK; i += 16) {
            s += g_psum[row * NBP + i];
            float v = g_pmax[row * NBP + i]; int ix = g_pidx[row * NBP + i];
            if (v > mv || (v == mv && ix < mi)) { mv = v; mi = ix; }
        }
        #pragma unroll
        for (int off = 8; off > 0; off >>= 1) {
            s += __shfl_xor_sync(0xffffffffu, s, off, 16);
            float v  = __shfl_xor_sync(0xffffffffu, mv, off, 16);
            int   i2 = __shfl_xor_sync(0xffffffffu, mi, off, 16);
            if (v > mv || (v == mv && i2 < mi)) { mv = v; mi = i2; }
        }
        if (l16 == 0) { sIS[row] = 1.0f / s; sAm[row] = mi; }
        __syncthreads();
    }
    if (MODE == 1 && tprev >= 0) {
        int row = tid >> 4, l16 = tid & 15;
        float s = 0.f;
        for (int i = l16; i < NBLK; i += 16) s += g_psum[row * NBP + i];
        #pragma unroll
        for (int off = 8; off > 0; off >>= 1)
            s += __shfl_xor_sync(0xffffffffu, s, off, 16);
        if (l16 == 0) sIS[row] = 1.0f / s;
        __syncthreads();
    }

    // ---- folded y-write for step t-1 ----
    if (MODE != 2 && tprev >= 0) {
        constexpr int LO   = (MODE == 0) ? 0 : 6283;
        constexpr int SPAN = (MODE == 0) ? 6283 : (NF4 - 6283);
        int total = 32 * SPAN;
        for (int idx = bx * 512 + tid; idx < total; idx += 128 * 512) {
            int row = idx / SPAN;
            int q = LO + (idx - row * SPAN);
            float4 v = *(const float4*)(g_E + (long)row * VPAD + q * 4);
            float inv = sIS[row];
            float* dst = out_y + ((long)row * T + tprev) * VOCAB;
            int c = q * 4;
            if (c + 3 < VOCAB) {
                dst[c] = v.x * inv; dst[c + 1] = v.y * inv;
                dst[c + 2] = v.z * inv; dst[c + 3] = v.w * inv;
            } else {
                if (c < VOCAB) dst[c] = v.x * inv;
                if (c + 1 < VOCAB) dst[c + 1] = v.y * inv;
                if (c + 2 < VOCAB) dst[c + 2] = v.z * inv;
            }
        }
    }

    // ---- MODE 2: per-row inv from layer-0 partials ----
    if (MODE == 2) {
        if (tid < 128) {
            int row = tid >> 2, qq = tid & 3;
            float s = 0.f;
            #pragma unroll 8
            for (int i = 0; i < 32; i++) s += g_ps0[row * 128 + qq * 32 + i];
            s += __shfl_xor_sync(0xffffffffu, s, 1);
            s += __shfl_xor_sync(0xffffffffu, s, 2);
            if (qq == 0) sInv[row] = 1.0f / s;
        }
        __syncthreads();
    }

    // ---- stage A matrices ----
    if (MODE == 2) {
        #pragma unroll
        for (int i = 0; i < 8; i++) {
            int q = tid + i * 512;
            int rr = q >> 7, cc = q & 127;
            float4 e = ((const float4*)g_e0)[q];
            float iv = sInv[rr];
            float4 xv;
            xv.x = tanhf(e.x * iv); xv.y = tanhf(e.y * iv);
            xv.z = tanhf(e.z * iv); xv.w = tanhf(e.w * iv);
            ((float4*)(sA1 + rr * 516))[cc] = xv;
        }
    } else if (MODE == 0 && tprev >= 0) {
        // x_cur = emb[argmax] gathered directly
        #pragma unroll
        for (int i = 0; i < 8; i++) {
            int q = tid + i * 512;
            int rr = q >> 7, cc = q & 127;
            ((float4*)(sA1 + rr * 516))[cc] =
                ((const float4*)(emb + (long)sAm[rr] * 512))[cc];
        }
    } else {
        const float4* gA1 = (const float4*)A1;
        #pragma unroll
        for (int i = 0; i < 8; i++) {
            int q = tid + i * 512;
            ((float4*)(sA1 + (q >> 7) * 516))[q & 127] = gA1[q];
        }
    }
    if (DUAL) {
        const float4* gA2 = (const float4*)A2;
        #pragma unroll
        for (int i = 0; i < 8; i++) {
            int q = tid + i * 512;
            ((float4*)(sA2 + (q >> 7) * 516))[q & 127] = gA2[q];
        }
    }
    #pragma unroll
    for (int i = 0; i < 4; i++) {
        int q = tid + i * 512;
        int kk = q >> 2, jj = q & 3;
        sW1[jj * 516 + kk] = W1[kk * 512 + jb + jj];
        if (DUAL) sW2[jj * 516 + kk] = W2[kk * 512 + jb + jj];
    }
    __syncthreads();

    // ---- compute: K quarter of 128 per thread, 4 accumulators ----
    float ac0 = 0.f, ac1 = 0.f, ac2 = 0.f, ac3 = 0.f;
    {
        const float4* a1 = (const float4*)(sA1 + r * 516) + quarter * 32;
        const float4* w1 = (const float4*)(sW1 + jl * 516) + quarter * 32;
        #pragma unroll
        for (int k = 0; k < 32; k += 4) {
            float4 x0 = a1[k],     y0 = w1[k];
            float4 x1v = a1[k + 1], y1 = w1[k + 1];
            float4 x2 = a1[k + 2], y2 = w1[k + 2];
            float4 x3 = a1[k + 3], y3 = w1[k + 3];
            ac0 = fmaf(x0.x, y0.x, ac0); ac0 = fmaf(x0.y, y0.y, ac0);
            ac0 = fmaf(x0.z, y0.z, ac0); ac0 = fmaf(x0.w, y0.w, ac0);
            ac1 = fmaf(x1v.x, y1.x, ac1); ac1 = fmaf(x1v.y, y1.y, ac1);
            ac1 = fmaf(x1v.z, y1.z, ac1); ac1 = fmaf(x1v.w, y1.w, ac1);
            ac2 = fmaf(x2.x, y2.x, ac2); ac2 = fmaf(x2.y, y2.y, ac2);
            ac2 = fmaf(x2.z, y2.z, ac2); ac2 = fmaf(x2.w, y2.w, ac2);
            ac3 = fmaf(x3.x, y3.x, ac3); ac3 = fmaf(x3.y, y3.y, ac3);
            ac3 = fmaf(x3.w, y3.w, ac3); ac3 = fmaf(x3.z, y3.z, ac3);
        }
    }
    if (DUAL) {
        const float4* a2 = (const float4*)(sA2 + r * 516) + quarter * 32;
        const float4* w2 = (const float4*)(sW2 + jl * 516) + quarter * 32;
        #pragma unroll
        for (int k = 0; k < 32; k += 4) {
            float4 x0 = a2[k],     y0 = w2[k];
            float4 x1v = a2[k + 1], y1 = w2[k + 1];
            float4 x2 = a2[k + 2], y2 = w2[k + 2];
            float4 x3 = a2[k + 3], y3 = w2[k + 3];
            ac0 = fmaf(x0.x, y0.x, ac0); ac0 = fmaf(x0.y, y0.y, ac0);
            ac0 = fmaf(x0.z, y0.z, ac0); ac0 = fmaf(x0.w, y0.w, ac0);
            ac1 = fmaf(x1v.x, y1.x, ac1); ac1 = fmaf(x1v.y, y1.y, ac1);
            ac1 = fmaf(x1v.z, y1.z, ac1); ac1 = fmaf(x1v.w, y1.w, ac1);
            ac2 = fmaf(x2.x, y2.x, ac2); ac2 = fmaf(x2.y, y2.y, ac2);
            ac2 = fmaf(x2.z, y2.z, ac2); ac2 = fmaf(x2.w, y2.w, ac2);
            ac3 = fmaf(x3.x, y3.x, ac3); ac3 = fmaf(x3.y, y3.y, ac3);
            ac3 = fmaf(x3.w, y3.w, ac3); ac3 = fmaf(x3.z, y3.z, ac3);
        }
    }
    sRed[quarter * 128 + sub] = (ac0 + ac1) + (ac2 + ac3);
    __syncthreads();

    // ---- epilogue (first 128 threads) ----
    if (tid < 128) {
        float o = sRed[tid] + sRed[128 + tid] + sRed[256 + tid] + sRed[384 + tid]
                + bias[jb + jl];
        if (MODE == 0) {
            o = tanhf(o);
            outp[r * 512 + jb + jl] = o;
        } else if (MODE == 1) {
            float e = __expf(o);                 // |logits0| small: shift-free safe
            g_e0[r * 512 + jb + jl] = e;
            float v = e;
            v += __shfl_down_sync(0xffffffffu, v, 2);
            v += __shfl_down_sync(0xffffffffu, v, 1);
            if ((tid & 3) == 0) g_ps0[r * 128 + bx] = v;
        } else {
            o = tanhf(o);
            outp[r * 512 + jb + jl] = o;
            out_h[((long)r * T + t) * 512 + jb + jl] = o;
            sH[r * 5 + jl] = o;
        }
    }
    if (MODE == 2) {
        __syncthreads();
        if (tid < 128) {
            int hl = tid >> 6, rem = tid & 63;
            int ps = rem & 1, rr = rem >> 1;
            int c0i = jb + ps * 2;
            float v0 = sH[rr * 5 + ps * 2], v1 = sH[rr * 5 + ps * 2 + 1];
            float h0f = bf_hi(v0), h1f = bf_hi(v1);
            uint32_t pk = hl ? pk_bf2(v0 - h0f, v1 - h1f) : pk_bf2(h0f, h1f);
            int ks = c0i >> 4, kk = c0i & 15;
            int hcol = (kk >> 3) & 1, g = (kk >> 1) & 3;
            int lane = (rr & 7) * 4 + g;
            int reg = hcol * 2 + ((rr >> 3) & 1);
            int mtile = rr >> 4;
            ((uint32_t*)g_Af)[(((hl * 32 + ks) * 2 + mtile) * 32 + lane) * 4 + reg] = pk;
        }
    }
}

// ---------------- big GEMM: 197 x 256 threads, exp epilogue + partials ----------------
__global__ void __launch_bounds__(256) k_big() {
    int tid = threadIdx.x, w = tid >> 5, lane = tid & 31;
    int bx = blockIdx.x;
    int n8base = bx * 32 + w * 4;
    float acc[2][4][4];
    #pragma unroll
    for (int m = 0; m < 2; m++)
        #pragma unroll
        for (int n = 0; n < 4; n++)
            #pragma unroll
            for (int rr = 0; rr < 4; rr++) acc[m][n][rr] = 0.f;

    #pragma unroll 2
    for (int ks = 0; ks < 32; ks++) {
        uint4 ah0 = g_Af[(ks * 2 + 0) * 32 + lane];
        uint4 ah1 = g_Af[(ks * 2 + 1) * 32 + lane];
        uint4 al0 = g_Af[((32 + ks) * 2 + 0) * 32 + lane];
        uint4 al1 = g_Af[((32 + ks) * 2 + 1) * 32 + lane];
        uint4 bv[4];
        #pragma unroll
        for (int n = 0; n < 4; n++)
            bv[n] = g_Bf[((long)ks * NB8 + n8base + n) * 32 + lane];
        #pragma unroll
        for (int n = 0; n < 4; n++) {
            mma_bf16(acc[0][n], ah0, bv[n].x, bv[n].y);
            mma_bf16(acc[1][n], ah1, bv[n].x, bv[n].y);
            mma_bf16(acc[0][n], al0, bv[n].x, bv[n].y);
            mma_bf16(acc[1][n], al1, bv[n].x, bv[n].y);
            mma_bf16(acc[0][n], ah0, bv[n].z, bv[n].w);
            mma_bf16(acc[1][n], ah1, bv[n].z, bv[n].w);
        }
    }

    __shared__ float s_sum[8][32];
    __shared__ float s_max[8][32];
    __shared__ int   s_idx[8][32];
    int colw = bx * 256 + w * 32;
    float rsum[4] = {0.f, 0.f, 0.f, 0.f};
    float rmax[4] = {-3e38f, -3e38f, -3e38f, -3e38f};
    int   ridx[4] = {0, 0, 0, 0};

    #pragma unroll
    for (int m = 0; m < 2; m++) {
        #pragma unroll
        for (int n = 0; n < 4; n++) {
            int c0 = colw + n * 8 + ((lane & 3) << 1);
            float bias0 = g_c1p[c0], bias1 = g_c1p[c0 + 1];
            {
                float l0 = acc[m][n][0] + bias0, l1 = acc[m][n][1] + bias1;
                float e0 = __expf(l0), e1 = __expf(l1);
                int row = m * 16 + (lane >> 2);
                *(float2*)&g_E[(long)row * VPAD + c0] = make_float2(e0, e1);
                int slot = m * 2;
                rsum[slot] += e0 + e1;
                if (l0 > rmax[slot] || (l0 == rmax[slot] && c0 < ridx[slot])) { rmax[slot] = l0; ridx[slot] = c0; }
                if (l1 > rmax[slot] || (l1 == rmax[slot] && c0 + 1 < ridx[slot])) { rmax[slot] = l1; ridx[slot] = c0 + 1; }
            }
            {
                float l0 = acc[m][n][2] + bias0, l1 = acc[m][n][3] + bias1;
                float e0 = __expf(l0), e1 = __expf(l1);
                int row = m * 16 + (lane >> 2) + 8;
                *(float2*)&g_E[(long)row * VPAD + c0] = make_float2(e0, e1);
                int slot = m * 2 + 1;
                rsum[slot] += e0 + e1;
                if (l0 > rmax[slot] || (l0 == rmax[slot] && c0 < ridx[slot])) { rmax[slot] = l0; ridx[slot] = c0; }
                if (l1 > rmax[slot] || (l1 == rmax[slot] && c0 + 1 < ridx[slot])) { rmax[slot] = l1; ridx[slot] = c0 + 1; }
            }
        }
    }
    #pragma unroll
    for (int off = 1; off <= 2; off <<= 1) {
        #pragma unroll
        for (int slot = 0; slot < 4; slot++) {
            rsum[slot] += __shfl_xor_sync(0xffffffffu, rsum[slot], off);
            float v = __shfl_xor_sync(0xffffffffu, rmax[slot], off);
            int   i = __shfl_xor_sync(0xffffffffu, ridx[slot], off);
            if (v > rmax[slot] || (v == rmax[slot] && i < ridx[slot])) { rmax[slot] = v; ridx[slot] = i; }
        }
    }
    if ((lane & 3) == 0) {
        #pragma unroll
        for (int slot = 0; slot < 4; slot++) {
            int row = (slot >> 1) * 16 + (lane >> 2) + (slot & 1) * 8;
            s_sum[w][row] = rsum[slot];
            s_max[w][row] = rmax[slot];
            s_idx[w][row] = ridx[slot];
        }
    }
    __syncthreads();
    if (tid < 32) {
        int row = tid;
        float ps = 0.f, pv = -3e38f; int pi = 0;
        #pragma unroll
        for (int ww = 0; ww < 8; ww++) {
            ps += s_sum[ww][row];
            float v = s_max[ww][row]; int i = s_idx[ww][row];
            if (v > pv || (v == pv && i < pi)) { pv = v; pi = i; }
        }
        g_psum[row * NBP + bx] = ps;
        g_pmax[row * NBP + bx] = pv;
        g_pidx[row * NBP + bx] = pi;
    }
}

// ---------------- final combine (once, after loop) ----------------
__global__ void __launch_bounds__(128) k_comb() {
    __shared__ float rs[128];
    int row = blockIdx.x, tid = threadIdx.x;
    float s = 0.f;
    for (int i = tid; i < NBLK; i += 128) s += g_psum[row * NBP + i];
    rs[tid] = s;
    __syncthreads();
    for (int st = 64; st > 0; st >>= 1) {
        if (tid < st) rs[tid] += rs[tid + st];
        __syncthreads();
    }
    if (tid == 0) g_invS[row] = 1.0f / rs[0];
}

// ---------------- final-step y write ----------------
__global__ void k_writey(float* __restrict__ out_y, int t, int T) {
    int b = blockIdx.y;
    float inv = g_invS[b];
    const float* erow = &g_E[(long)b * VPAD];
    float* yrow = &out_y[((long)b * T + t) * VOCAB];
    for (int j = blockIdx.x * blockDim.x + threadIdx.x; j < VOCAB; j += gridDim.x * blockDim.x)
        yrow[j] = erow[j] * inv;
}

// ---------------- host launcher ----------------
extern "C" void kernel_launch(void* const* d_in, const int* in_sizes, int n_in,
                              void* d_out, int out_size) {
    const int*   x      = (const int*)d_in[0];
    const float* h_prev = (const float*)d_in[3];
    const float* emb    = (const float*)d_in[4];
    const float* U0     = (const float*)d_in[5];
    const float* W0     = (const float*)d_in[6];
    const float* b0     = (const float*)d_in[7];
    const float* V0     = (const float*)d_in[8];
    const float* c0     = (const float*)d_in[9];
    const float* U1     = (const float*)d_in[10];
    const float* W1     = (const float*)d_in[11];
    const float* b1     = (const float*)d_in[12];
    const float* V1     = (const float*)d_in[13];
    const float* c1     = (const float*)d_in[14];

    float* out = (float*)d_out;
    int T = out_size / (BB * (HH + VOCAB));
    float* out_h = out;
    float* out_y = out + (long)BB * T * HH;

    float *p_xcur, *p_h0, *p_h1;
    cudaGetSymbolAddress((void**)&p_xcur, g_xcur);
    cudaGetSymbolAddress((void**)&p_h0,   g_h0s);
    cudaGetSymbolAddress((void**)&p_h1,   g_h1s);

    const int SMEM_DUAL   = (16512 * 2 + 2064 * 2 + 512 + 160 + 32 + 64 + 32) * 4;
    const int SMEM_SINGLE = (16512 + 2064 + 512 + 160 + 32 + 64 + 32) * 4;
    static bool attr_set = false;
    if (!attr_set) {
        cudaFuncSetAttribute(k_cellx<0>, cudaFuncAttributeMaxDynamicSharedMemorySize, SMEM_DUAL);
        cudaFuncSetAttribute(k_cellx<1>, cudaFuncAttributeMaxDynamicSharedMemorySize, SMEM_SINGLE);
        cudaFuncSetAttribute(k_cellx<2>, cudaFuncAttributeMaxDynamicSharedMemorySize, SMEM_DUAL);
        attr_set = true;
    }

    k_init<<<BB, 512>>>(x, h_prev, emb);
    k_pack_c1<<<(VPAD + 255) / 256, 256>>>(c1);
    k_pack_b<<<dim3(VPAD / 256, 32), 256>>>(V1);

    for (int t = 0; t < T; t++) {
        int cur = t & 1;
        float* h0c = p_h0 + cur * BB * HH;
        float* h0n = p_h0 + (cur ^ 1) * BB * HH;
        float* h1c = p_h1 + cur * BB * HH;
        float* h1n = p_h1 + (cur ^ 1) * BB * HH;

        // cell0: per-block comb + x=emb[am]; h0 = tanh(x@U0 + h0p@W0 + b0); y(t-1) lo half
        k_cellx<0><<<128, 512, SMEM_DUAL>>>(p_xcur, h0c, U0, W0, b0, h0n,
                                            nullptr, out_y, emb, t, t - 1, T);
        // head0: per-block invS; e0 = exp(h0@V0 + c0) + partials; y(t-1) hi half
        k_cellx<1><<<128, 512, SMEM_SINGLE>>>(h0n, nullptr, V0, nullptr, c0, nullptr,
                                              nullptr, out_y, emb, t, t - 1, T);
        // cell1: inline x1; h1 = tanh(x1@U1 + h1p@W1 + b1); out_h + frag pack
        k_cellx<2><<<128, 512, SMEM_DUAL>>>(nullptr, h1c, U1, W1, b1, h1n,
                                            out_h, nullptr, emb, t, -1, T);
        // logits1 -> exp + partials
        k_big<<<NBLK, 256>>>();
    }
    // final step: invS + y write
    k_comb<<<BB, 128>>>();
    k_writey<<<dim3(64, BB), 256>>>(out_y, T - 1, T);
}

// round 14
// speedup vs baseline: 1.2433x; 1.2433x over previous
#include <cuda_runtime.h>
#include <cuda_bf16.h>
#include <math.h>
#include <stdint.h>

#define BB 32
#define HH 512
#define VOCAB 50257
#define VPAD  50432          // multiple of 256
#define NB8   (VPAD/8)       // 6304 fragment columns
#define NBLK  (VPAD/256)     // 197 big-gemm blocks (256 cols each)
#define NBP   208            // padded partial stride
#define NF4   12565          // float4 groups covering VOCAB

// ---------------- device scratch ----------------
__device__ float g_xcur[BB * HH];
__device__ float g_h0s[2][BB * HH];
__device__ float g_h1s[2][BB * HH];
__device__ float g_e0[BB * HH];                // exp(logits0)
__device__ float g_ps0[BB * 128];              // layer-0 partial row sums per block
__device__ uint4 g_Af[2 * 32 * 2 * 32];        // [hl][ks][m][lane] A fragments for k_big
__device__ uint4 g_Bf[(long)32 * NB8 * 32];    // [ks][n8][lane] -> {bh0,bh1,bl0,bl1}
__device__ float g_c1p[VPAD];
__device__ float g_E[BB * VPAD];               // exp(logits1)
__device__ float g_psum[BB * NBP];
__device__ float g_pmax[BB * NBP];
__device__ int   g_pidx[BB * NBP];
__device__ float g_invS[BB];

// ---------------- helpers ----------------
__device__ __forceinline__ uint32_t pk_bf2(float a, float b) {
    uint32_t ua = (uint32_t)__bfloat16_as_ushort(__float2bfloat16_rn(a));
    uint32_t ub = (uint32_t)__bfloat16_as_ushort(__float2bfloat16_rn(b));
    return ua | (ub << 16);
}
__device__ __forceinline__ float bf_hi(float v) {
    return __bfloat162float(__float2bfloat16_rn(v));
}
__device__ __forceinline__ void mma_bf16(float* d, const uint4& a, uint32_t b0, uint32_t b1) {
    asm volatile(
        "mma.sync.aligned.m16n8k16.row.col.f32.bf16.bf16.f32 "
        "{%0,%1,%2,%3},{%4,%5,%6,%7},{%8,%9},{%0,%1,%2,%3};\n"
        : "+f"(d[0]), "+f"(d[1]), "+f"(d[2]), "+f"(d[3])
        : "r"(a.x), "r"(a.y), "r"(a.z), "r"(a.w), "r"(b0), "r"(b1));
}

// ---------------- one-time kernels ----------------
__global__ void k_init(const int* __restrict__ x, const float* __restrict__ h_prev,
                       const float* __restrict__ emb) {
    int b = blockIdx.x, j = threadIdx.x;
    g_xcur[b * HH + j]   = emb[(long)x[b] * HH + j];
    g_h0s[0][b * HH + j] = h_prev[b * HH + j];
    g_h1s[0][b * HH + j] = h_prev[b * HH + j];
}

__global__ void k_pack_c1(const float* __restrict__ c1) {
    int i = blockIdx.x * blockDim.x + threadIdx.x;
    if (i < VPAD) g_c1p[i] = (i < VOCAB) ? c1[i] : -1e30f;
}

__global__ void k_pack_b(const float* __restrict__ V1) {
    __shared__ float sv[16][257];
    int bx = blockIdx.x, ks = blockIdx.y, tid = threadIdx.x;
    int cbase = bx * 256;
    #pragma unroll
    for (int r = 0; r < 16; r++) {
        int col = cbase + tid;
        int k = ks * 16 + r;
        sv[r][tid] = (col < VOCAB) ? V1[(long)k * VOCAB + col] : 0.0f;
    }
    __syncthreads();
    for (int e = tid; e < 1024; e += 256) {
        int lane = e & 31, n8l = e >> 5;
        int colL = n8l * 8 + (lane >> 2);
        int rr = (lane & 3) * 2;
        float v0 = sv[rr][colL],     v1 = sv[rr + 1][colL];
        float v8 = sv[rr + 8][colL], v9 = sv[rr + 9][colL];
        float h0 = bf_hi(v0), h1 = bf_hi(v1), h8 = bf_hi(v8), h9 = bf_hi(v9);
        uint4 o;
        o.x = pk_bf2(h0, h1);
        o.y = pk_bf2(h8, h9);
        o.z = pk_bf2(v0 - h0, v1 - h1);
        o.w = pk_bf2(v8 - h8, v9 - h9);
        g_Bf[((long)ks * NB8 + bx * 32 + n8l) * 32 + lane] = o;
    }
}

// ---------------- small GEMM: full staging, 512 threads, 4-way split-K ----------------
// MODE 0: cell0  h0n = tanh(x@U0 + h0@W0 + b0)      + y(t-1) first half
// MODE 1: head0  e0 = exp(h0n@V0 + c0), partials    + y(t-1) second half
// MODE 2: cell1  inv from ps0; x1 = tanh(e0*inv) staged inline;
//                h1n = tanh(x1@U1 + h1@W1 + b1) + out_h + frag pack
template<int MODE>
__global__ void __launch_bounds__(512) k_cellx(
        const float* __restrict__ A1, const float* __restrict__ A2,
        const float* __restrict__ W1, const float* __restrict__ W2,
        const float* __restrict__ bias, float* __restrict__ outp,
        float* __restrict__ out_h, float* __restrict__ out_y,
        int t, int tprev, int T) {
    constexpr bool DUAL = (MODE != 1);
    extern __shared__ float sm[];
    float* sA1 = sm;                                   // 32 x 516
    float* sA2 = DUAL ? (sm + 16512) : nullptr;        // 32 x 516
    float* sW1 = sm + (DUAL ? 33024 : 16512);          // 4 x 516
    float* sW2 = DUAL ? (sW1 + 2064) : nullptr;        // 4 x 516
    float* sRed = sW1 + (DUAL ? 4128 : 2064);          // 512
    float* sH  = sRed + 512;                           // 32 x 5
    float* sInv = sH + 160;                            // 32

    int tid = threadIdx.x;
    int bx = blockIdx.x;
    int jb = bx * 4;
    int quarter = tid >> 7;
    int sub  = tid & 127;
    int jl = sub & 3, r = sub >> 2;

    // ---- folded y-write for step t-1 ----
    if (MODE != 2 && tprev >= 0) {
        constexpr int LO   = (MODE == 0) ? 0 : 6283;
        constexpr int SPAN = (MODE == 0) ? 6283 : (NF4 - 6283);
        int total = 32 * SPAN;
        for (int idx = bx * 512 + tid; idx < total; idx += 128 * 512) {
            int row = idx / SPAN;
            int q = LO + (idx - row * SPAN);
            float4 v = *(const float4*)(g_E + (long)row * VPAD + q * 4);
            float inv = g_invS[row];
            float* dst = out_y + ((long)row * T + tprev) * VOCAB;
            int c = q * 4;
            if (c + 3 < VOCAB) {
                dst[c] = v.x * inv; dst[c + 1] = v.y * inv;
                dst[c + 2] = v.z * inv; dst[c + 3] = v.w * inv;
            } else {
                if (c < VOCAB) dst[c] = v.x * inv;
                if (c + 1 < VOCAB) dst[c + 1] = v.y * inv;
                if (c + 2 < VOCAB) dst[c + 2] = v.z * inv;
            }
        }
    }

    // ---- MODE 2: per-row inv from layer-0 partials ----
    if (MODE == 2) {
        if (tid < 128) {
            int row = tid >> 2, qq = tid & 3;
            float s = 0.f;
            #pragma unroll 8
            for (int i = 0; i < 32; i++) s += g_ps0[row * 128 + qq * 32 + i];
            s += __shfl_xor_sync(0xffffffffu, s, 1);
            s += __shfl_xor_sync(0xffffffffu, s, 2);
            if (qq == 0) sInv[row] = 1.0f / s;
        }
        __syncthreads();
    }

    // ---- stage A matrices ----
    if (MODE == 2) {
        #pragma unroll
        for (int i = 0; i < 8; i++) {
            int q = tid + i * 512;
            int rr = q >> 7, cc = q & 127;
            float4 e = ((const float4*)g_e0)[q];
            float iv = sInv[rr];
            float4 xv;
            xv.x = tanhf(e.x * iv); xv.y = tanhf(e.y * iv);
            xv.z = tanhf(e.z * iv); xv.w = tanhf(e.w * iv);
            ((float4*)(sA1 + rr * 516))[cc] = xv;
        }
    } else {
        const float4* gA1 = (const float4*)A1;
        #pragma unroll
        for (int i = 0; i < 8; i++) {
            int q = tid + i * 512;
            ((float4*)(sA1 + (q >> 7) * 516))[q & 127] = gA1[q];
        }
    }
    if (DUAL) {
        const float4* gA2 = (const float4*)A2;
        #pragma unroll
        for (int i = 0; i < 8; i++) {
            int q = tid + i * 512;
            ((float4*)(sA2 + (q >> 7) * 516))[q & 127] = gA2[q];
        }
    }
    #pragma unroll
    for (int i = 0; i < 4; i++) {
        int q = tid + i * 512;
        int kk = q >> 2, jj = q & 3;
        sW1[jj * 516 + kk] = W1[kk * 512 + jb + jj];
        if (DUAL) sW2[jj * 516 + kk] = W2[kk * 512 + jb + jj];
    }
    __syncthreads();

    // ---- compute: K quarter of 128 per thread, 4 accumulators ----
    float ac0 = 0.f, ac1 = 0.f, ac2 = 0.f, ac3 = 0.f;
    {
        const float4* a1 = (const float4*)(sA1 + r * 516) + quarter * 32;
        const float4* w1 = (const float4*)(sW1 + jl * 516) + quarter * 32;
        #pragma unroll
        for (int k = 0; k < 32; k += 4) {
            float4 x0 = a1[k],     y0 = w1[k];
            float4 x1v = a1[k + 1], y1 = w1[k + 1];
            float4 x2 = a1[k + 2], y2 = w1[k + 2];
            float4 x3 = a1[k + 3], y3 = w1[k + 3];
            ac0 = fmaf(x0.x, y0.x, ac0); ac0 = fmaf(x0.y, y0.y, ac0);
            ac0 = fmaf(x0.z, y0.z, ac0); ac0 = fmaf(x0.w, y0.w, ac0);
            ac1 = fmaf(x1v.x, y1.x, ac1); ac1 = fmaf(x1v.y, y1.y, ac1);
            ac1 = fmaf(x1v.z, y1.z, ac1); ac1 = fmaf(x1v.w, y1.w, ac1);
            ac2 = fmaf(x2.x, y2.x, ac2); ac2 = fmaf(x2.y, y2.y, ac2);
            ac2 = fmaf(x2.z, y2.z, ac2); ac2 = fmaf(x2.w, y2.w, ac2);
            ac3 = fmaf(x3.x, y3.x, ac3); ac3 = fmaf(x3.y, y3.y, ac3);
            ac3 = fmaf(x3.w, y3.w, ac3); ac3 = fmaf(x3.z, y3.z, ac3);
        }
    }
    if (DUAL) {
        const float4* a2 = (const float4*)(sA2 + r * 516) + quarter * 32;
        const float4* w2 = (const float4*)(sW2 + jl * 516) + quarter * 32;
        #pragma unroll
        for (int k = 0; k < 32; k += 4) {
            float4 x0 = a2[k],     y0 = w2[k];
            float4 x1v = a2[k + 1], y1 = w2[k + 1];
            float4 x2 = a2[k + 2], y2 = w2[k + 2];
            float4 x3 = a2[k + 3], y3 = w2[k + 3];
            ac0 = fmaf(x0.x, y0.x, ac0); ac0 = fmaf(x0.y, y0.y, ac0);
            ac0 = fmaf(x0.z, y0.z, ac0); ac0 = fmaf(x0.w, y0.w, ac0);
            ac1 = fmaf(x1v.x, y1.x, ac1); ac1 = fmaf(x1v.y, y1.y, ac1);
            ac1 = fmaf(x1v.z, y1.z, ac1); ac1 = fmaf(x1v.w, y1.w, ac1);
            ac2 = fmaf(x2.x, y2.x, ac2); ac2 = fmaf(x2.y, y2.y, ac2);
            ac2 = fmaf(x2.z, y2.z, ac2); ac2 = fmaf(x2.w, y2.w, ac2);
            ac3 = fmaf(x3.x, y3.x, ac3); ac3 = fmaf(x3.y, y3.y, ac3);
            ac3 = fmaf(x3.w, y3.w, ac3); ac3 = fmaf(x3.z, y3.z, ac3);
        }
    }
    sRed[quarter * 128 + sub] = (ac0 + ac1) + (ac2 + ac3);
    __syncthreads();

    // ---- epilogue (first 128 threads) ----
    if (tid < 128) {
        float o = sRed[tid] + sRed[128 + tid] + sRed[256 + tid] + sRed[384 + tid]
                + bias[jb + jl];
        if (MODE == 0) {
            o = tanhf(o);
            outp[r * 512 + jb + jl] = o;
        } else if (MODE == 1) {
            float e = __expf(o);                 // |logits0| small: shift-free safe
            g_e0[r * 512 + jb + jl] = e;
            float v = e;
            v += __shfl_down_sync(0xffffffffu, v, 2);
            v += __shfl_down_sync(0xffffffffu, v, 1);
            if ((tid & 3) == 0) g_ps0[r * 128 + bx] = v;
        } else {
            o = tanhf(o);
            outp[r * 512 + jb + jl] = o;
            out_h[((long)r * T + t) * 512 + jb + jl] = o;
            sH[r * 5 + jl] = o;
        }
    }
    if (MODE == 2) {
        __syncthreads();
        if (tid < 128) {
            int hl = tid >> 6, rem = tid & 63;
            int ps = rem & 1, rr = rem >> 1;
            int c0i = jb + ps * 2;
            float v0 = sH[rr * 5 + ps * 2], v1 = sH[rr * 5 + ps * 2 + 1];
            float h0f = bf_hi(v0), h1f = bf_hi(v1);
            uint32_t pk = hl ? pk_bf2(v0 - h0f, v1 - h1f) : pk_bf2(h0f, h1f);
            int ks = c0i >> 4, kk = c0i & 15;
            int hcol = (kk >> 3) & 1, g = (kk >> 1) & 3;
            int lane = (rr & 7) * 4 + g;
            int reg = hcol * 2 + ((rr >> 3) & 1);
            int mtile = rr >> 4;
            ((uint32_t*)g_Af)[(((hl * 32 + ks) * 2 + mtile) * 32 + lane) * 4 + reg] = pk;
        }
    }
}

// ---------------- big GEMM: 197 x 256 threads, double-buffered ks pipeline ----------------
__global__ void __launch_bounds__(256) k_big() {
    int tid = threadIdx.x, w = tid >> 5, lane = tid & 31;
    int bx = blockIdx.x;
    int n8base = bx * 32 + w * 4;
    float acc[2][4][4];
    #pragma unroll
    for (int m = 0; m < 2; m++)
        #pragma unroll
        for (int n = 0; n < 4; n++)
            #pragma unroll
            for (int rr = 0; rr < 4; rr++) acc[m][n][rr] = 0.f;

    // software pipeline: prefetch ks+1's A and B fragments while issuing ks's MMAs
    uint4 bv[2][4];
    uint4 ah0[2], ah1[2], al0[2], al1[2];
    #pragma unroll
    for (int n = 0; n < 4; n++)
        bv[0][n] = g_Bf[((long)0 * NB8 + n8base + n) * 32 + lane];
    ah0[0] = g_Af[0 * 32 + lane];
    ah1[0] = g_Af[1 * 32 + lane];
    al0[0] = g_Af[(32 * 2 + 0) * 32 + lane];
    al1[0] = g_Af[(32 * 2 + 1) * 32 + lane];

    #pragma unroll 2
    for (int ks = 0; ks < 32; ks++) {
        int cur = ks & 1, nxt = cur ^ 1;
        if (ks < 31) {
            int kn = ks + 1;
            #pragma unroll
            for (int n = 0; n < 4; n++)
                bv[nxt][n] = g_Bf[((long)kn * NB8 + n8base + n) * 32 + lane];
            ah0[nxt] = g_Af[(kn * 2 + 0) * 32 + lane];
            ah1[nxt] = g_Af[(kn * 2 + 1) * 32 + lane];
            al0[nxt] = g_Af[((32 + kn) * 2 + 0) * 32 + lane];
            al1[nxt] = g_Af[((32 + kn) * 2 + 1) * 32 + lane];
        }
        #pragma unroll
        for (int n = 0; n < 4; n++) {
            mma_bf16(acc[0][n], ah0[cur], bv[cur][n].x, bv[cur][n].y);
            mma_bf16(acc[1][n], ah1[cur], bv[cur][n].x, bv[cur][n].y);
            mma_bf16(acc[0][n], al0[cur], bv[cur][n].x, bv[cur][n].y);
            mma_bf16(acc[1][n], al1[cur], bv[cur][n].x, bv[cur][n].y);
            mma_bf16(acc[0][n], ah0[cur], bv[cur][n].z, bv[cur][n].w);
            mma_bf16(acc[1][n], ah1[cur], bv[cur][n].z, bv[cur][n].w);
        }
    }

    __shared__ float s_sum[8][32];
    __shared__ float s_max[8][32];
    __shared__ int   s_idx[8][32];
    int colw = bx * 256 + w * 32;
    float rsum[4] = {0.f, 0.f, 0.f, 0.f};
    float rmax[4] = {-3e38f, -3e38f, -3e38f, -3e38f};
    int   ridx[4] = {0, 0, 0, 0};

    #pragma unroll
    for (int m = 0; m < 2; m++) {
        #pragma unroll
        for (int n = 0; n < 4; n++) {
            int c0 = colw + n * 8 + ((lane & 3) << 1);
            float bias0 = g_c1p[c0], bias1 = g_c1p[c0 + 1];
            {
                float l0 = acc[m][n][0] + bias0, l1 = acc[m][n][1] + bias1;
                float e0 = __expf(l0), e1 = __expf(l1);
                int row = m * 16 + (lane >> 2);
                *(float2*)&g_E[(long)row * VPAD + c0] = make_float2(e0, e1);
                int slot = m * 2;
                rsum[slot] += e0 + e1;
                if (l0 > rmax[slot] || (l0 == rmax[slot] && c0 < ridx[slot])) { rmax[slot] = l0; ridx[slot] = c0; }
                if (l1 > rmax[slot] || (l1 == rmax[slot] && c0 + 1 < ridx[slot])) { rmax[slot] = l1; ridx[slot] = c0 + 1; }
            }
            {
                float l0 = acc[m][n][2] + bias0, l1 = acc[m][n][3] + bias1;
                float e0 = __expf(l0), e1 = __expf(l1);
                int row = m * 16 + (lane >> 2) + 8;
                *(float2*)&g_E[(long)row * VPAD + c0] = make_float2(e0, e1);
                int slot = m * 2 + 1;
                rsum[slot] += e0 + e1;
                if (l0 > rmax[slot] || (l0 == rmax[slot] && c0 < ridx[slot])) { rmax[slot] = l0; ridx[slot] = c0; }
                if (l1 > rmax[slot] || (l1 == rmax[slot] && c0 + 1 < ridx[slot])) { rmax[slot] = l1; ridx[slot] = c0 + 1; }
            }
        }
    }
    #pragma unroll
    for (int off = 1; off <= 2; off <<= 1) {
        #pragma unroll
        for (int slot = 0; slot < 4; slot++) {
            rsum[slot] += __shfl_xor_sync(0xffffffffu, rsum[slot], off);
            float v = __shfl_xor_sync(0xffffffffu, rmax[slot], off);
            int   i = __shfl_xor_sync(0xffffffffu, ridx[slot], off);
            if (v > rmax[slot] || (v == rmax[slot] && i < ridx[slot])) { rmax[slot] = v; ridx[slot] = i; }
        }
    }
    if ((lane & 3) == 0) {
        #pragma unroll
        for (int slot = 0; slot < 4; slot++) {
            int row = (slot >> 1) * 16 + (lane >> 2) + (slot & 1) * 8;
            s_sum[w][row] = rsum[slot];
            s_max[w][row] = rmax[slot];
            s_idx[w][row] = ridx[slot];
        }
    }
    __syncthreads();
    if (tid < 32) {
        int row = tid;
        float ps = 0.f, pv = -3e38f; int pi = 0;
        #pragma unroll
        for (int ww = 0; ww < 8; ww++) {
            ps += s_sum[ww][row];
            float v = s_max[ww][row]; int i = s_idx[ww][row];
            if (v > pv || (v == pv && i < pi)) { pv = v; pi = i; }
        }
        g_psum[row * NBP + bx] = ps;
        g_pmax[row * NBP + bx] = pv;
        g_pidx[row * NBP + bx] = pi;
    }
}

// ---------------- combine partials: invS + argmax + embed feedback ----------------
__global__ void __launch_bounds__(128) k_comb(const float* __restrict__ emb) {
    __shared__ float rs[128], rv[128];
    __shared__ int   ri[128];
    int row = blockIdx.x, tid = threadIdx.x;
    float s = 0.f, mv = -3e38f; int mi = 0;
    for (int i = tid; i < NBLK; i += 128) {
        s += g_psum[row * NBP + i];
        float v = g_pmax[row * NBP + i]; int ix = g_pidx[row * NBP + i];
        if (v > mv || (v == mv && ix < mi)) { mv = v; mi = ix; }
    }
    rs[tid] = s; rv[tid] = mv; ri[tid] = mi;
    __syncthreads();
    for (int st = 64; st > 0; st >>= 1) {
        if (tid < st) {
            rs[tid] += rs[tid + st];
            float v = rv[tid + st]; int i = ri[tid + st];
            if (v > rv[tid] || (v == rv[tid] && i < ri[tid])) { rv[tid] = v; ri[tid] = i; }
        }
        __syncthreads();
    }
    if (tid == 0) g_invS[row] = 1.0f / rs[0];
    int am = ri[0];
    for (int j = tid; j < 512; j += 128)
        g_xcur[row * 512 + j] = emb[(long)am * 512 + j];
}

// ---------------- final-step y write ----------------
__global__ void k_writey(float* __restrict__ out_y, int t, int T) {
    int b = blockIdx.y;
    float inv = g_invS[b];
    const float* erow = &g_E[(long)b * VPAD];
    float* yrow = &out_y[((long)b * T + t) * VOCAB];
    for (int j = blockIdx.x * blockDim.x + threadIdx.x; j < VOCAB; j += gridDim.x * blockDim.x)
        yrow[j] = erow[j] * inv;
}

// ---------------- host launcher ----------------
extern "C" void kernel_launch(void* const* d_in, const int* in_sizes, int n_in,
                              void* d_out, int out_size) {
    const int*   x      = (const int*)d_in[0];
    const float* h_prev = (const float*)d_in[3];
    const float* emb    = (const float*)d_in[4];
    const float* U0     = (const float*)d_in[5];
    const float* W0     = (const float*)d_in[6];
    const float* b0     = (const float*)d_in[7];
    const float* V0     = (const float*)d_in[8];
    const float* c0     = (const float*)d_in[9];
    const float* U1     = (const float*)d_in[10];
    const float* W1     = (const float*)d_in[11];
    const float* b1     = (const float*)d_in[12];
    const float* V1     = (const float*)d_in[13];
    const float* c1     = (const float*)d_in[14];

    float* out = (float*)d_out;
    int T = out_size / (BB * (HH + VOCAB));
    float* out_h = out;
    float* out_y = out + (long)BB * T * HH;

    float *p_xcur, *p_h0, *p_h1;
    cudaGetSymbolAddress((void**)&p_xcur, g_xcur);
    cudaGetSymbolAddress((void**)&p_h0,   g_h0s);
    cudaGetSymbolAddress((void**)&p_h1,   g_h1s);

    const int SMEM_DUAL   = (16512 * 2 + 2064 * 2 + 512 + 160 + 32) * 4;   // 151424
    const int SMEM_SINGLE = (16512 + 2064 + 512 + 160 + 32) * 4;           //  77120
    static bool attr_set = false;
    if (!attr_set) {
        cudaFuncSetAttribute(k_cellx<0>, cudaFuncAttributeMaxDynamicSharedMemorySize, SMEM_DUAL);
        cudaFuncSetAttribute(k_cellx<1>, cudaFuncAttributeMaxDynamicSharedMemorySize, SMEM_SINGLE);
        cudaFuncSetAttribute(k_cellx<2>, cudaFuncAttributeMaxDynamicSharedMemorySize, SMEM_DUAL);
        attr_set = true;
    }

    k_init<<<BB, 512>>>(x, h_prev, emb);
    k_pack_c1<<<(VPAD + 255) / 256, 256>>>(c1);
    k_pack_b<<<dim3(VPAD / 256, 32), 256>>>(V1);

    for (int t = 0; t < T; t++) {
        int cur = t & 1;
        float* h0c = p_h0 + cur * BB * HH;
        float* h0n = p_h0 + (cur ^ 1) * BB * HH;
        float* h1c = p_h1 + cur * BB * HH;
        float* h1n = p_h1 + (cur ^ 1) * BB * HH;

        // h0 = tanh(x@U0 + h0p@W0 + b0)   (+ y(t-1) first half)
        k_cellx<0><<<128, 512, SMEM_DUAL>>>(p_xcur, h0c, U0, W0, b0, h0n,
                                            nullptr, out_y, t, t - 1, T);
        // e0 = exp(h0@V0 + c0) + partials (+ y(t-1) second half)
        k_cellx<1><<<128, 512, SMEM_SINGLE>>>(h0n, nullptr, V0, nullptr, c0, nullptr,
                                              nullptr, out_y, t, t - 1, T);
        // h1 = tanh(x1@U1 + h1p@W1 + b1) with inline x1; out_h + frag pack
        k_cellx<2><<<128, 512, SMEM_DUAL>>>(nullptr, h1c, U1, W1, b1, h1n,
                                            out_h, nullptr, t, -1, T);
        // logits1 -> exp + partials (pipelined)
        k_big<<<NBLK, 256>>>();
        // invS + argmax + feedback embed
        k_comb<<<BB, 128>>>(emb);
    }
    // final step's y
    k_writey<<<dim3(64, BB), 256>>>(out_y, T - 1, T);
}

// round 15
// speedup vs baseline: 1.2899x; 1.0374x over previous
#include <cuda_runtime.h>
#include <cuda_bf16.h>
#include <math.h>
#include <stdint.h>

#define BB 32
#define HH 512
#define VOCAB 50257
#define VPAD  50432          // multiple of 256
#define NB8   (VPAD/8)       // 6304 fragment columns
#define NBLK  (VPAD/256)     // 197 big-gemm blocks (256 cols each)
#define NBP   208            // padded partial stride
#define NF4   12565          // float4 groups covering VOCAB

// ---------------- device scratch ----------------
__device__ float g_xcur[BB * HH];
__device__ float g_h0s[2][BB * HH];
__device__ float g_h1s[2][BB * HH];
__device__ float g_e0[BB * HH];                // exp(logits0)
__device__ float g_ps0[BB * 128];              // layer-0 partial row sums per block
__device__ uint4 g_Af[2 * 32 * 2 * 32];        // [hl][ks][m][lane] A fragments for k_big
__device__ uint4 g_Bf[(long)32 * NB8 * 32];    // [ks][n8][lane] -> {bh0,bh1,bl0,bl1}
__device__ float g_c1p[VPAD];
__device__ float g_E[BB * VPAD];               // exp(logits1)
__device__ float g_psum[BB * NBP];
__device__ float g_pmax[BB * NBP];
__device__ int   g_pidx[BB * NBP];
__device__ float g_invS[BB];
__device__ float g_Wt[5][512 * 512];           // transposed weights: Wt[j][k] = W[k][j]

// ---------------- helpers ----------------
__device__ __forceinline__ uint32_t pk_bf2(float a, float b) {
    uint32_t ua = (uint32_t)__bfloat16_as_ushort(__float2bfloat16_rn(a));
    uint32_t ub = (uint32_t)__bfloat16_as_ushort(__float2bfloat16_rn(b));
    return ua | (ub << 16);
}
__device__ __forceinline__ float bf_hi(float v) {
    return __bfloat162float(__float2bfloat16_rn(v));
}
__device__ __forceinline__ void mma_bf16(float* d, const uint4& a, uint32_t b0, uint32_t b1) {
    asm volatile(
        "mma.sync.aligned.m16n8k16.row.col.f32.bf16.bf16.f32 "
        "{%0,%1,%2,%3},{%4,%5,%6,%7},{%8,%9},{%0,%1,%2,%3};\n"
        : "+f"(d[0]), "+f"(d[1]), "+f"(d[2]), "+f"(d[3])
        : "r"(a.x), "r"(a.y), "r"(a.z), "r"(a.w), "r"(b0), "r"(b1));
}

// ---------------- one-time kernels ----------------
__global__ void k_init(const int* __restrict__ x, const float* __restrict__ h_prev,
                       const float* __restrict__ emb) {
    int b = blockIdx.x, j = threadIdx.x;
    g_xcur[b * HH + j]   = emb[(long)x[b] * HH + j];
    g_h0s[0][b * HH + j] = h_prev[b * HH + j];
    g_h1s[0][b * HH + j] = h_prev[b * HH + j];
}

__global__ void k_pack_c1(const float* __restrict__ c1) {
    int i = blockIdx.x * blockDim.x + threadIdx.x;
    if (i < VPAD) g_c1p[i] = (i < VOCAB) ? c1[i] : -1e30f;
}

// tiled transpose of the 5 small weight matrices into g_Wt
__global__ void k_packw(const float* __restrict__ U0, const float* __restrict__ W0,
                        const float* __restrict__ V0, const float* __restrict__ U1,
                        const float* __restrict__ W1) {
    __shared__ float tile[32][33];
    const float* src;
    switch (blockIdx.z) {
        case 0: src = U0; break;
        case 1: src = W0; break;
        case 2: src = V0; break;
        case 3: src = U1; break;
        default: src = W1; break;
    }
    int tx = threadIdx.x, ty = threadIdx.y;
    int k0 = blockIdx.y * 32, j0 = blockIdx.x * 32;
    tile[ty][tx] = src[(k0 + ty) * 512 + j0 + tx];
    __syncthreads();
    g_Wt[blockIdx.z][(j0 + ty) * 512 + k0 + tx] = tile[tx][ty];
}

__global__ void k_pack_b(const float* __restrict__ V1) {
    __shared__ float sv[16][257];
    int bx = blockIdx.x, ks = blockIdx.y, tid = threadIdx.x;
    int cbase = bx * 256;
    #pragma unroll
    for (int r = 0; r < 16; r++) {
        int col = cbase + tid;
        int k = ks * 16 + r;
        sv[r][tid] = (col < VOCAB) ? V1[(long)k * VOCAB + col] : 0.0f;
    }
    __syncthreads();
    for (int e = tid; e < 1024; e += 256) {
        int lane = e & 31, n8l = e >> 5;
        int colL = n8l * 8 + (lane >> 2);
        int rr = (lane & 3) * 2;
        float v0 = sv[rr][colL],     v1 = sv[rr + 1][colL];
        float v8 = sv[rr + 8][colL], v9 = sv[rr + 9][colL];
        float h0 = bf_hi(v0), h1 = bf_hi(v1), h8 = bf_hi(v8), h9 = bf_hi(v9);
        uint4 o;
        o.x = pk_bf2(h0, h1);
        o.y = pk_bf2(h8, h9);
        o.z = pk_bf2(v0 - h0, v1 - h1);
        o.w = pk_bf2(v8 - h8, v9 - h9);
        g_Bf[((long)ks * NB8 + bx * 32 + n8l) * 32 + lane] = o;
    }
}

// ---------------- small GEMM: full staging (coalesced weights), 512 thr, 4-way split-K ----
// MODE 0: cell0  h0n = tanh(x@U0 + h0@W0 + b0)      + y(t-1) first half
// MODE 1: head0  e0 = exp(h0n@V0 + c0), partials    + y(t-1) second half
// MODE 2: cell1  inv from ps0; x1 = tanh(e0*inv) staged inline;
//                h1n = tanh(x1@U1 + h1@W1 + b1) + out_h + frag pack
template<int MODE>
__global__ void __launch_bounds__(512) k_cellx(
        const float* __restrict__ A1, const float* __restrict__ A2,
        const float* __restrict__ W1t, const float* __restrict__ W2t,
        const float* __restrict__ bias, float* __restrict__ outp,
        float* __restrict__ out_h, float* __restrict__ out_y,
        int t, int tprev, int T) {
    constexpr bool DUAL = (MODE != 1);
    extern __shared__ float sm[];
    float* sA1 = sm;                                   // 32 x 516
    float* sA2 = DUAL ? (sm + 16512) : nullptr;        // 32 x 516
    float* sW1 = sm + (DUAL ? 33024 : 16512);          // 4 x 516
    float* sW2 = DUAL ? (sW1 + 2064) : nullptr;        // 4 x 516
    float* sRed = sW1 + (DUAL ? 4128 : 2064);          // 512
    float* sH  = sRed + 512;                           // 32 x 5
    float* sInv = sH + 160;                            // 32

    int tid = threadIdx.x;
    int bx = blockIdx.x;
    int jb = bx * 4;
    int quarter = tid >> 7;
    int sub  = tid & 127;
    int jl = sub & 3, r = sub >> 2;

    // ---- folded y-write for step t-1 ----
    if (MODE != 2 && tprev >= 0) {
        constexpr int LO   = (MODE == 0) ? 0 : 6283;
        constexpr int SPAN = (MODE == 0) ? 6283 : (NF4 - 6283);
        int total = 32 * SPAN;
        for (int idx = bx * 512 + tid; idx < total; idx += 128 * 512) {
            int row = idx / SPAN;
            int q = LO + (idx - row * SPAN);
            float4 v = *(const float4*)(g_E + (long)row * VPAD + q * 4);
            float inv = g_invS[row];
            float* dst = out_y + ((long)row * T + tprev) * VOCAB;
            int c = q * 4;
            if (c + 3 < VOCAB) {
                dst[c] = v.x * inv; dst[c + 1] = v.y * inv;
                dst[c + 2] = v.z * inv; dst[c + 3] = v.w * inv;
            } else {
                if (c < VOCAB) dst[c] = v.x * inv;
                if (c + 1 < VOCAB) dst[c + 1] = v.y * inv;
                if (c + 2 < VOCAB) dst[c + 2] = v.z * inv;
            }
        }
    }

    // ---- MODE 2: per-row inv from layer-0 partials ----
    if (MODE == 2) {
        if (tid < 128) {
            int row = tid >> 2, qq = tid & 3;
            float s = 0.f;
            #pragma unroll 8
            for (int i = 0; i < 32; i++) s += g_ps0[row * 128 + qq * 32 + i];
            s += __shfl_xor_sync(0xffffffffu, s, 1);
            s += __shfl_xor_sync(0xffffffffu, s, 2);
            if (qq == 0) sInv[row] = 1.0f / s;
        }
        __syncthreads();
    }

    // ---- stage A matrices ----
    if (MODE == 2) {
        #pragma unroll
        for (int i = 0; i < 8; i++) {
            int q = tid + i * 512;
            int rr = q >> 7, cc = q & 127;
            float4 e = ((const float4*)g_e0)[q];
            float iv = sInv[rr];
            float4 xv;
            xv.x = tanhf(e.x * iv); xv.y = tanhf(e.y * iv);
            xv.z = tanhf(e.z * iv); xv.w = tanhf(e.w * iv);
            ((float4*)(sA1 + rr * 516))[cc] = xv;
        }
    } else {
        const float4* gA1 = (const float4*)A1;
        #pragma unroll
        for (int i = 0; i < 8; i++) {
            int q = tid + i * 512;
            ((float4*)(sA1 + (q >> 7) * 516))[q & 127] = gA1[q];
        }
    }
    if (DUAL) {
        const float4* gA2 = (const float4*)A2;
        #pragma unroll
        for (int i = 0; i < 8; i++) {
            int q = tid + i * 512;
            ((float4*)(sA2 + (q >> 7) * 516))[q & 127] = gA2[q];
        }
    }
    // ---- stage weight columns: coalesced rows of the transposed matrices ----
    {
        int jj = tid >> 7, kk = tid & 127;      // 4 rows x 128 float4
        ((float4*)(sW1 + jj * 516))[kk] =
            ((const float4*)(W1t + (long)(jb + jj) * 512))[kk];
        if (DUAL)
            ((float4*)(sW2 + jj * 516))[kk] =
                ((const float4*)(W2t + (long)(jb + jj) * 512))[kk];
    }
    __syncthreads();

    // ---- compute: K quarter of 128 per thread, 4 accumulators ----
    float ac0 = 0.f, ac1 = 0.f, ac2 = 0.f, ac3 = 0.f;
    {
        const float4* a1 = (const float4*)(sA1 + r * 516) + quarter * 32;
        const float4* w1 = (const float4*)(sW1 + jl * 516) + quarter * 32;
        #pragma unroll
        for (int k = 0; k < 32; k += 4) {
            float4 x0 = a1[k],     y0 = w1[k];
            float4 x1v = a1[k + 1], y1 = w1[k + 1];
            float4 x2 = a1[k + 2], y2 = w1[k + 2];
            float4 x3 = a1[k + 3], y3 = w1[k + 3];
            ac0 = fmaf(x0.x, y0.x, ac0); ac0 = fmaf(x0.y, y0.y, ac0);
            ac0 = fmaf(x0.z, y0.z, ac0); ac0 = fmaf(x0.w, y0.w, ac0);
            ac1 = fmaf(x1v.x, y1.x, ac1); ac1 = fmaf(x1v.y, y1.y, ac1);
            ac1 = fmaf(x1v.z, y1.z, ac1); ac1 = fmaf(x1v.w, y1.w, ac1);
            ac2 = fmaf(x2.x, y2.x, ac2); ac2 = fmaf(x2.y, y2.y, ac2);
            ac2 = fmaf(x2.z, y2.z, ac2); ac2 = fmaf(x2.w, y2.w, ac2);
            ac3 = fmaf(x3.x, y3.x, ac3); ac3 = fmaf(x3.y, y3.y, ac3);
            ac3 = fmaf(x3.w, y3.w, ac3); ac3 = fmaf(x3.z, y3.z, ac3);
        }
    }
    if (DUAL) {
        const float4* a2 = (const float4*)(sA2 + r * 516) + quarter * 32;
        const float4* w2 = (const float4*)(sW2 + jl * 516) + quarter * 32;
        #pragma unroll
        for (int k = 0; k < 32; k += 4) {
            float4 x0 = a2[k],     y0 = w2[k];
            float4 x1v = a2[k + 1], y1 = w2[k + 1];
            float4 x2 = a2[k + 2], y2 = w2[k + 2];
            float4 x3 = a2[k + 3], y3 = w2[k + 3];
            ac0 = fmaf(x0.x, y0.x, ac0); ac0 = fmaf(x0.y, y0.y, ac0);
            ac0 = fmaf(x0.z, y0.z, ac0); ac0 = fmaf(x0.w, y0.w, ac0);
            ac1 = fmaf(x1v.x, y1.x, ac1); ac1 = fmaf(x1v.y, y1.y, ac1);
            ac1 = fmaf(x1v.z, y1.z, ac1); ac1 = fmaf(x1v.w, y1.w, ac1);
            ac2 = fmaf(x2.x, y2.x, ac2); ac2 = fmaf(x2.y, y2.y, ac2);
            ac2 = fmaf(x2.z, y2.z, ac2); ac2 = fmaf(x2.w, y2.w, ac2);
            ac3 = fmaf(x3.x, y3.x, ac3); ac3 = fmaf(x3.y, y3.y, ac3);
            ac3 = fmaf(x3.w, y3.w, ac3); ac3 = fmaf(x3.z, y3.z, ac3);
        }
    }
    sRed[quarter * 128 + sub] = (ac0 + ac1) + (ac2 + ac3);
    __syncthreads();

    // ---- epilogue (first 128 threads) ----
    if (tid < 128) {
        float o = sRed[tid] + sRed[128 + tid] + sRed[256 + tid] + sRed[384 + tid]
                + bias[jb + jl];
        if (MODE == 0) {
            o = tanhf(o);
            outp[r * 512 + jb + jl] = o;
        } else if (MODE == 1) {
            float e = __expf(o);                 // |logits0| small: shift-free safe
            g_e0[r * 512 + jb + jl] = e;
            float v = e;
            v += __shfl_down_sync(0xffffffffu, v, 2);
            v += __shfl_down_sync(0xffffffffu, v, 1);
            if ((tid & 3) == 0) g_ps0[r * 128 + bx] = v;
        } else {
            o = tanhf(o);
            outp[r * 512 + jb + jl] = o;
            out_h[((long)r * T + t) * 512 + jb + jl] = o;
            sH[r * 5 + jl] = o;
        }
    }
    if (MODE == 2) {
        __syncthreads();
        if (tid < 128) {
            int hl = tid >> 6, rem = tid & 63;
            int ps = rem & 1, rr = rem >> 1;
            int c0i = jb + ps * 2;
            float v0 = sH[rr * 5 + ps * 2], v1 = sH[rr * 5 + ps * 2 + 1];
            float h0f = bf_hi(v0), h1f = bf_hi(v1);
            uint32_t pk = hl ? pk_bf2(v0 - h0f, v1 - h1f) : pk_bf2(h0f, h1f);
            int ks = c0i >> 4, kk = c0i & 15;
            int hcol = (kk >> 3) & 1, g = (kk >> 1) & 3;
            int lane = (rr & 7) * 4 + g;
            int reg = hcol * 2 + ((rr >> 3) & 1);
            int mtile = rr >> 4;
            ((uint32_t*)g_Af)[(((hl * 32 + ks) * 2 + mtile) * 32 + lane) * 4 + reg] = pk;
        }
    }
}

// ---------------- big GEMM: 197 x 256 threads, double-buffered ks pipeline ----------------
__global__ void __launch_bounds__(256) k_big() {
    int tid = threadIdx.x, w = tid >> 5, lane = tid & 31;
    int bx = blockIdx.x;
    int n8base = bx * 32 + w * 4;
    float acc[2][4][4];
    #pragma unroll
    for (int m = 0; m < 2; m++)
        #pragma unroll
        for (int n = 0; n < 4; n++)
            #pragma unroll
            for (int rr = 0; rr < 4; rr++) acc[m][n][rr] = 0.f;

    uint4 bv[2][4];
    uint4 ah0[2], ah1[2], al0[2], al1[2];
    #pragma unroll
    for (int n = 0; n < 4; n++)
        bv[0][n] = g_Bf[((long)0 * NB8 + n8base + n) * 32 + lane];
    ah0[0] = g_Af[0 * 32 + lane];
    ah1[0] = g_Af[1 * 32 + lane];
    al0[0] = g_Af[(32 * 2 + 0) * 32 + lane];
    al1[0] = g_Af[(32 * 2 + 1) * 32 + lane];

    #pragma unroll 2
    for (int ks = 0; ks < 32; ks++) {
        int cur = ks & 1, nxt = cur ^ 1;
        if (ks < 31) {
            int kn = ks + 1;
            #pragma unroll
            for (int n = 0; n < 4; n++)
                bv[nxt][n] = g_Bf[((long)kn * NB8 + n8base + n) * 32 + lane];
            ah0[nxt] = g_Af[(kn * 2 + 0) * 32 + lane];
            ah1[nxt] = g_Af[(kn * 2 + 1) * 32 + lane];
            al0[nxt] = g_Af[((32 + kn) * 2 + 0) * 32 + lane];
            al1[nxt] = g_Af[((32 + kn) * 2 + 1) * 32 + lane];
        }
        #pragma unroll
        for (int n = 0; n < 4; n++) {
            mma_bf16(acc[0][n], ah0[cur], bv[cur][n].x, bv[cur][n].y);
            mma_bf16(acc[1][n], ah1[cur], bv[cur][n].x, bv[cur][n].y);
            mma_bf16(acc[0][n], al0[cur], bv[cur][n].x, bv[cur][n].y);
            mma_bf16(acc[1][n], al1[cur], bv[cur][n].x, bv[cur][n].y);
            mma_bf16(acc[0][n], ah0[cur], bv[cur][n].z, bv[cur][n].w);
            mma_bf16(acc[1][n], ah1[cur], bv[cur][n].z, bv[cur][n].w);
        }
    }

    __shared__ float s_sum[8][32];
    __shared__ float s_max[8][32];
    __shared__ int   s_idx[8][32];
    int colw = bx * 256 + w * 32;
    float rsum[4] = {0.f, 0.f, 0.f, 0.f};
    float rmax[4] = {-3e38f, -3e38f, -3e38f, -3e38f};
    int   ridx[4] = {0, 0, 0, 0};

    #pragma unroll
    for (int m = 0; m < 2; m++) {
        #pragma unroll
        for (int n = 0; n < 4; n++) {
            int c0 = colw + n * 8 + ((lane & 3) << 1);
            float bias0 = g_c1p[c0], bias1 = g_c1p[c0 + 1];
            {
                float l0 = acc[m][n][0] + bias0, l1 = acc[m][n][1] + bias1;
                float e0 = __expf(l0), e1 = __expf(l1);
                int row = m * 16 + (lane >> 2);
                *(float2*)&g_E[(long)row * VPAD + c0] = make_float2(e0, e1);
                int slot = m * 2;
                rsum[slot] += e0 + e1;
                if (l0 > rmax[slot] || (l0 == rmax[slot] && c0 < ridx[slot])) { rmax[slot] = l0; ridx[slot] = c0; }
                if (l1 > rmax[slot] || (l1 == rmax[slot] && c0 + 1 < ridx[slot])) { rmax[slot] = l1; ridx[slot] = c0 + 1; }
            }
            {
                float l0 = acc[m][n][2] + bias0, l1 = acc[m][n][3] + bias1;
                float e0 = __expf(l0), e1 = __expf(l1);
                int row = m * 16 + (lane >> 2) + 8;
                *(float2*)&g_E[(long)row * VPAD + c0] = make_float2(e0, e1);
                int slot = m * 2 + 1;
                rsum[slot] += e0 + e1;
                if (l0 > rmax[slot] || (l0 == rmax[slot] && c0 < ridx[slot])) { rmax[slot] = l0; ridx[slot] = c0; }
                if (l1 > rmax[slot] || (l1 == rmax[slot] && c0 + 1 < ridx[slot])) { rmax[slot] = l1; ridx[slot] = c0 + 1; }
            }
        }
    }
    #pragma unroll
    for (int off = 1; off <= 2; off <<= 1) {
        #pragma unroll
        for (int slot = 0; slot < 4; slot++) {
            rsum[slot] += __shfl_xor_sync(0xffffffffu, rsum[slot], off);
            float v = __shfl_xor_sync(0xffffffffu, rmax[slot], off);
            int   i = __shfl_xor_sync(0xffffffffu, ridx[slot], off);
            if (v > rmax[slot] || (v == rmax[slot] && i < ridx[slot])) { rmax[slot] = v; ridx[slot] = i; }
        }
    }
    if ((lane & 3) == 0) {
        #pragma unroll
        for (int slot = 0; slot < 4; slot++) {
            int row = (slot >> 1) * 16 + (lane >> 2) + (slot & 1) * 8;
            s_sum[w][row] = rsum[slot];
            s_max[w][row] = rmax[slot];
            s_idx[w][row] = ridx[slot];
        }
    }
    __syncthreads();
    if (tid < 32) {
        int row = tid;
        float ps = 0.f, pv = -3e38f; int pi = 0;
        #pragma unroll
        for (int ww = 0; ww < 8; ww++) {
            ps += s_sum[ww][row];
            float v = s_max[ww][row]; int i = s_idx[ww][row];
            if (v > pv || (v == pv && i < pi)) { pv = v; pi = i; }
        }
        g_psum[row * NBP + bx] = ps;
        g_pmax[row * NBP + bx] = pv;
        g_pidx[row * NBP + bx] = pi;
    }
}

// ---------------- combine partials: invS + argmax + embed feedback ----------------
__global__ void __launch_bounds__(128) k_comb(const float* __restrict__ emb) {
    __shared__ float rs[128], rv[128];
    __shared__ int   ri[128];
    int row = blockIdx.x, tid = threadIdx.x;
    float s = 0.f, mv = -3e38f; int mi = 0;
    for (int i = tid; i < NBLK; i += 128) {
        s += g_psum[row * NBP + i];
        float v = g_pmax[row * NBP + i]; int ix = g_pidx[row * NBP + i];
        if (v > mv || (v == mv && ix < mi)) { mv = v; mi = ix; }
    }
    rs[tid] = s; rv[tid] = mv; ri[tid] = mi;
    __syncthreads();
    for (int st = 64; st > 0; st >>= 1) {
        if (tid < st) {
            rs[tid] += rs[tid + st];
            float v = rv[tid + st]; int i = ri[tid + st];
            if (v > rv[tid] || (v == rv[tid] && i < ri[tid])) { rv[tid] = v; ri[tid] = i; }
        }
        __syncthreads();
    }
    if (tid == 0) g_invS[row] = 1.0f / rs[0];
    int am = ri[0];
    for (int j = tid; j < 512; j += 128)
        g_xcur[row * 512 + j] = emb[(long)am * 512 + j];
}

// ---------------- final-step y write ----------------
__global__ void k_writey(float* __restrict__ out_y, int t, int T) {
    int b = blockIdx.y;
    float inv = g_invS[b];
    const float* erow = &g_E[(long)b * VPAD];
    float* yrow = &out_y[((long)b * T + t) * VOCAB];
    for (int j = blockIdx.x * blockDim.x + threadIdx.x; j < VOCAB; j += gridDim.x * blockDim.x)
        yrow[j] = erow[j] * inv;
}

// ---------------- host launcher ----------------
extern "C" void kernel_launch(void* const* d_in, const int* in_sizes, int n_in,
                              void* d_out, int out_size) {
    const int*   x      = (const int*)d_in[0];
    const float* h_prev = (const float*)d_in[3];
    const float* emb    = (const float*)d_in[4];
    const float* U0     = (const float*)d_in[5];
    const float* W0     = (const float*)d_in[6];
    const float* b0     = (const float*)d_in[7];
    const float* V0     = (const float*)d_in[8];
    const float* c0     = (const float*)d_in[9];
    const float* U1     = (const float*)d_in[10];
    const float* W1     = (const float*)d_in[11];
    const float* b1     = (const float*)d_in[12];
    const float* V1     = (const float*)d_in[13];
    const float* c1     = (const float*)d_in[14];

    float* out = (float*)d_out;
    int T = out_size / (BB * (HH + VOCAB));
    float* out_h = out;
    float* out_y = out + (long)BB * T * HH;

    float *p_xcur, *p_h0, *p_h1, *p_Wt;
    cudaGetSymbolAddress((void**)&p_xcur, g_xcur);
    cudaGetSymbolAddress((void**)&p_h0,   g_h0s);
    cudaGetSymbolAddress((void**)&p_h1,   g_h1s);
    cudaGetSymbolAddress((void**)&p_Wt,   g_Wt);
    const float* U0t = p_Wt + 0L * 512 * 512;
    const float* W0t = p_Wt + 1L * 512 * 512;
    const float* V0t = p_Wt + 2L * 512 * 512;
    const float* U1t = p_Wt + 3L * 512 * 512;
    const float* W1t = p_Wt + 4L * 512 * 512;

    const int SMEM_DUAL   = (16512 * 2 + 2064 * 2 + 512 + 160 + 32) * 4;   // 151424
    const int SMEM_SINGLE = (16512 + 2064 + 512 + 160 + 32) * 4;           //  77120
    static bool attr_set = false;
    if (!attr_set) {
        cudaFuncSetAttribute(k_cellx<0>, cudaFuncAttributeMaxDynamicSharedMemorySize, SMEM_DUAL);
        cudaFuncSetAttribute(k_cellx<1>, cudaFuncAttributeMaxDynamicSharedMemorySize, SMEM_SINGLE);
        cudaFuncSetAttribute(k_cellx<2>, cudaFuncAttributeMaxDynamicSharedMemorySize, SMEM_DUAL);
        attr_set = true;
    }

    k_init<<<BB, 512>>>(x, h_prev, emb);
    k_pack_c1<<<(VPAD + 255) / 256, 256>>>(c1);
    k_packw<<<dim3(16, 16, 5), dim3(32, 32)>>>(U0, W0, V0, U1, W1);
    k_pack_b<<<dim3(VPAD / 256, 32), 256>>>(V1);

    for (int t = 0; t < T; t++) {
        int cur = t & 1;
        float* h0c = p_h0 + cur * BB * HH;
        float* h0n = p_h0 + (cur ^ 1) * BB * HH;
        float* h1c = p_h1 + cur * BB * HH;
        float* h1n = p_h1 + (cur ^ 1) * BB * HH;

        // h0 = tanh(x@U0 + h0p@W0 + b0)   (+ y(t-1) first half)
        k_cellx<0><<<128, 512, SMEM_DUAL>>>(p_xcur, h0c, U0t, W0t, b0, h0n,
                                            nullptr, out_y, t, t - 1, T);
        // e0 = exp(h0@V0 + c0) + partials (+ y(t-1) second half)
        k_cellx<1><<<128, 512, SMEM_SINGLE>>>(h0n, nullptr, V0t, nullptr, c0, nullptr,
                                              nullptr, out_y, t, t - 1, T);
        // h1 = tanh(x1@U1 + h1p@W1 + b1) with inline x1; out_h + frag pack
        k_cellx<2><<<128, 512, SMEM_DUAL>>>(nullptr, h1c, U1t, W1t, b1, h1n,
                                            out_h, nullptr, t, -1, T);
        // logits1 -> exp + partials (pipelined)
        k_big<<<NBLK, 256>>>();
        // invS + argmax + feedback embed
        k_comb<<<BB, 128>>>(emb);
    }
    // final step's y
    k_writey<<<dim3(64, BB), 256>>>(out_y, T - 1, T);
}

// round 16
// speedup vs baseline: 1.3698x; 1.0620x over previous
#include <cuda_runtime.h>
#include <cuda_bf16.h>
#include <math.h>
#include <stdint.h>

#define BB 32
#define HH 512
#define VOCAB 50257
#define VPAD  50432          // multiple of 256
#define NB8   (VPAD/8)       // 6304 fragment columns
#define NBLK  (VPAD/256)     // 197 big-gemm blocks (256 cols each)
#define NBP   208            // padded partial stride
#define NF4   12565          // float4 groups covering VOCAB

// ---------------- device scratch ----------------
__device__ float g_xcur[BB * HH];
__device__ float g_h0s[2][BB * HH];
__device__ float g_h1s[2][BB * HH];
__device__ float g_e0[BB * HH];                // exp(logits0)
__device__ float g_ps0[BB * 128];              // layer-0 partial row sums per block
__device__ uint4 g_Af[2 * 32 * 2 * 32];        // [hl][ks][m][lane] A fragments for k_big
__device__ uint4 g_Bf[(long)32 * NB8 * 32];    // [ks][n8][lane] -> {bh0,bh1,bl0,bl1}
__device__ float g_c1p[VPAD];
__device__ float g_E[BB * VPAD];               // exp(logits1)
__device__ float g_psum[BB * NBP];
__device__ float g_pmax[BB * NBP];
__device__ int   g_pidx[BB * NBP];
__device__ float g_invS[BB];
__device__ float g_Wt[5][512 * 512];           // transposed weights: Wt[j][k] = W[k][j]

// ---------------- helpers ----------------
__device__ __forceinline__ uint32_t pk_bf2(float a, float b) {
    uint32_t ua = (uint32_t)__bfloat16_as_ushort(__float2bfloat16_rn(a));
    uint32_t ub = (uint32_t)__bfloat16_as_ushort(__float2bfloat16_rn(b));
    return ua | (ub << 16);
}
__device__ __forceinline__ float bf_hi(float v) {
    return __bfloat162float(__float2bfloat16_rn(v));
}
__device__ __forceinline__ void mma_bf16(float* d, const uint4& a, uint32_t b0, uint32_t b1) {
    asm volatile(
        "mma.sync.aligned.m16n8k16.row.col.f32.bf16.bf16.f32 "
        "{%0,%1,%2,%3},{%4,%5,%6,%7},{%8,%9},{%0,%1,%2,%3};\n"
        : "+f"(d[0]), "+f"(d[1]), "+f"(d[2]), "+f"(d[3])
        : "r"(a.x), "r"(a.y), "r"(a.z), "r"(a.w), "r"(b0), "r"(b1));
}

// ---------------- one-time kernels ----------------
__global__ void k_init(const int* __restrict__ x, const float* __restrict__ h_prev,
                       const float* __restrict__ emb) {
    int b = blockIdx.x, j = threadIdx.x;
    g_xcur[b * HH + j]   = emb[(long)x[b] * HH + j];
    g_h0s[0][b * HH + j] = h_prev[b * HH + j];
    g_h1s[0][b * HH + j] = h_prev[b * HH + j];
}

__global__ void k_pack_c1(const float* __restrict__ c1) {
    int i = blockIdx.x * blockDim.x + threadIdx.x;
    if (i < VPAD) g_c1p[i] = (i < VOCAB) ? c1[i] : -1e30f;
}

// tiled transpose of the 5 small weight matrices into g_Wt
__global__ void k_packw(const float* __restrict__ U0, const float* __restrict__ W0,
                        const float* __restrict__ V0, const float* __restrict__ U1,
                        const float* __restrict__ W1) {
    __shared__ float tile[32][33];
    const float* src;
    switch (blockIdx.z) {
        case 0: src = U0; break;
        case 1: src = W0; break;
        case 2: src = V0; break;
        case 3: src = U1; break;
        default: src = W1; break;
    }
    int tx = threadIdx.x, ty = threadIdx.y;
    int k0 = blockIdx.y * 32, j0 = blockIdx.x * 32;
    tile[ty][tx] = src[(k0 + ty) * 512 + j0 + tx];
    __syncthreads();
    g_Wt[blockIdx.z][(j0 + ty) * 512 + k0 + tx] = tile[tx][ty];
}

__global__ void k_pack_b(const float* __restrict__ V1) {
    __shared__ float sv[16][257];
    int bx = blockIdx.x, ks = blockIdx.y, tid = threadIdx.x;
    int cbase = bx * 256;
    #pragma unroll
    for (int r = 0; r < 16; r++) {
        int col = cbase + tid;
        int k = ks * 16 + r;
        sv[r][tid] = (col < VOCAB) ? V1[(long)k * VOCAB + col] : 0.0f;
    }
    __syncthreads();
    for (int e = tid; e < 1024; e += 256) {
        int lane = e & 31, n8l = e >> 5;
        int colL = n8l * 8 + (lane >> 2);
        int rr = (lane & 3) * 2;
        float v0 = sv[rr][colL],     v1 = sv[rr + 1][colL];
        float v8 = sv[rr + 8][colL], v9 = sv[rr + 9][colL];
        float h0 = bf_hi(v0), h1 = bf_hi(v1), h8 = bf_hi(v8), h9 = bf_hi(v9);
        uint4 o;
        o.x = pk_bf2(h0, h1);
        o.y = pk_bf2(h8, h9);
        o.z = pk_bf2(v0 - h0, v1 - h1);
        o.w = pk_bf2(v8 - h8, v9 - h9);
        g_Bf[((long)ks * NB8 + bx * 32 + n8l) * 32 + lane] = o;
    }
}

// ---------------- small GEMM: PDL prologue + full staging, 512 thr, 4-way split-K ----
// MODE 0: cell0  h0n = tanh(x@U0 + h0@W0 + b0)
// MODE 1: head0  [prologue: y(t-1) first half]  e0 = exp(h0n@V0 + c0) + partials
// MODE 2: cell1  [prologue: y(t-1) second half] inv from ps0; x1 inline;
//                h1n = tanh(x1@U1 + h1@W1 + b1) + out_h + frag pack
template<int MODE>
__global__ void __launch_bounds__(512) k_cellx(
        const float* __restrict__ A1, const float* __restrict__ A2,
        const float* __restrict__ W1t, const float* __restrict__ W2t,
        const float* __restrict__ bias, float* __restrict__ outp,
        float* __restrict__ out_h, float* __restrict__ out_y,
        int t, int tprev, int T) {
    constexpr bool DUAL = (MODE != 1);
    extern __shared__ float sm[];
    float* sA1 = sm;                                   // 32 x 516
    float* sA2 = DUAL ? (sm + 16512) : nullptr;        // 32 x 516
    float* sW1 = sm + (DUAL ? 33024 : 16512);          // 4 x 516
    float* sW2 = DUAL ? (sW1 + 2064) : nullptr;        // 4 x 516
    float* sRed = sW1 + (DUAL ? 4128 : 2064);          // 512
    float* sH  = sRed + 512;                           // 32 x 5
    float* sInv = sH + 160;                            // 32

    int tid = threadIdx.x;
    int bx = blockIdx.x;
    int jb = bx * 4;
    int quarter = tid >> 7;
    int sub  = tid & 127;
    int jl = sub & 3, r = sub >> 2;

    // ================= PDL prologue (independent of immediate predecessor) =====
    // stage weight columns: coalesced rows of the transposed matrices
    {
        int jj = tid >> 7, kk = tid & 127;      // 4 rows x 128 float4
        ((float4*)(sW1 + jj * 516))[kk] =
            ((const float4*)(W1t + (long)(jb + jj) * 512))[kk];
        if (DUAL)
            ((float4*)(sW2 + jj * 516))[kk] =
                ((const float4*)(W2t + (long)(jb + jj) * 512))[kk];
    }
    // folded y-write for step t-1 (inputs are >= 2 kernels old: safe pre-sync)
    if (MODE != 0 && tprev >= 0) {
        constexpr int LO   = (MODE == 1) ? 0 : 6283;
        constexpr int SPAN = (MODE == 1) ? 6283 : (NF4 - 6283);
        int total = 32 * SPAN;
        for (int idx = bx * 512 + tid; idx < total; idx += 128 * 512) {
            int row = idx / SPAN;
            int q = LO + (idx - row * SPAN);
            float4 v = *(const float4*)(g_E + (long)row * VPAD + q * 4);
            float inv = g_invS[row];
            float* dst = out_y + ((long)row * T + tprev) * VOCAB;
            int c = q * 4;
            if (c + 3 < VOCAB) {
                dst[c] = v.x * inv; dst[c + 1] = v.y * inv;
                dst[c + 2] = v.z * inv; dst[c + 3] = v.w * inv;
            } else {
                if (c < VOCAB) dst[c] = v.x * inv;
                if (c + 1 < VOCAB) dst[c + 1] = v.y * inv;
                if (c + 2 < VOCAB) dst[c + 2] = v.z * inv;
            }
        }
    }
    // ================= wait for predecessor, then release successor ============
    cudaGridDependencySynchronize();
    cudaTriggerProgrammaticLaunchCompletion();

    // ---- MODE 2: per-row inv from layer-0 partials (from head0, just synced) ----
    if (MODE == 2) {
        if (tid < 128) {
            int row = tid >> 2, qq = tid & 3;
            float s = 0.f;
            #pragma unroll 8
            for (int i = 0; i < 32; i++) s += g_ps0[row * 128 + qq * 32 + i];
            s += __shfl_xor_sync(0xffffffffu, s, 1);
            s += __shfl_xor_sync(0xffffffffu, s, 2);
            if (qq == 0) sInv[row] = 1.0f / s;
        }
        __syncthreads();
    }

    // ---- stage A matrices ----
    if (MODE == 2) {
        #pragma unroll
        for (int i = 0; i < 8; i++) {
            int q = tid + i * 512;
            int rr = q >> 7, cc = q & 127;
            float4 e = ((const float4*)g_e0)[q];
            float iv = sInv[rr];
            float4 xv;
            xv.x = tanhf(e.x * iv); xv.y = tanhf(e.y * iv);
            xv.z = tanhf(e.z * iv); xv.w = tanhf(e.w * iv);
            ((float4*)(sA1 + rr * 516))[cc] = xv;
        }
    } else {
        const float4* gA1 = (const float4*)A1;
        #pragma unroll
        for (int i = 0; i < 8; i++) {
            int q = tid + i * 512;
            ((float4*)(sA1 + (q >> 7) * 516))[q & 127] = gA1[q];
        }
    }
    if (DUAL) {
        const float4* gA2 = (const float4*)A2;
        #pragma unroll
        for (int i = 0; i < 8; i++) {
            int q = tid + i * 512;
            ((float4*)(sA2 + (q >> 7) * 516))[q & 127] = gA2[q];
        }
    }
    __syncthreads();

    // ---- compute: K quarter of 128 per thread, 4 accumulators ----
    float ac0 = 0.f, ac1 = 0.f, ac2 = 0.f, ac3 = 0.f;
    {
        const float4* a1 = (const float4*)(sA1 + r * 516) + quarter * 32;
        const float4* w1 = (const float4*)(sW1 + jl * 516) + quarter * 32;
        #pragma unroll
        for (int k = 0; k < 32; k += 4) {
            float4 x0 = a1[k],     y0 = w1[k];
            float4 x1v = a1[k + 1], y1 = w1[k + 1];
            float4 x2 = a1[k + 2], y2 = w1[k + 2];
            float4 x3 = a1[k + 3], y3 = w1[k + 3];
            ac0 = fmaf(x0.x, y0.x, ac0); ac0 = fmaf(x0.y, y0.y, ac0);
            ac0 = fmaf(x0.z, y0.z, ac0); ac0 = fmaf(x0.w, y0.w, ac0);
            ac1 = fmaf(x1v.x, y1.x, ac1); ac1 = fmaf(x1v.y, y1.y, ac1);
            ac1 = fmaf(x1v.z, y1.z, ac1); ac1 = fmaf(x1v.w, y1.w, ac1);
            ac2 = fmaf(x2.x, y2.x, ac2); ac2 = fmaf(x2.y, y2.y, ac2);
            ac2 = fmaf(x2.z, y2.z, ac2); ac2 = fmaf(x2.w, y2.w, ac2);
            ac3 = fmaf(x3.x, y3.x, ac3); ac3 = fmaf(x3.y, y3.y, ac3);
            ac3 = fmaf(x3.w, y3.w, ac3); ac3 = fmaf(x3.z, y3.z, ac3);
        }
    }
    if (DUAL) {
        const float4* a2 = (const float4*)(sA2 + r * 516) + quarter * 32;
        const float4* w2 = (const float4*)(sW2 + jl * 516) + quarter * 32;
        #pragma unroll
        for (int k = 0; k < 32; k += 4) {
            float4 x0 = a2[k],     y0 = w2[k];
            float4 x1v = a2[k + 1], y1 = w2[k + 1];
            float4 x2 = a2[k + 2], y2 = w2[k + 2];
            float4 x3 = a2[k + 3], y3 = w2[k + 3];
            ac0 = fmaf(x0.x, y0.x, ac0); ac0 = fmaf(x0.y, y0.y, ac0);
            ac0 = fmaf(x0.z, y0.z, ac0); ac0 = fmaf(x0.w, y0.w, ac0);
            ac1 = fmaf(x1v.x, y1.x, ac1); ac1 = fmaf(x1v.y, y1.y, ac1);
            ac1 = fmaf(x1v.z, y1.z, ac1); ac1 = fmaf(x1v.w, y1.w, ac1);
            ac2 = fmaf(x2.x, y2.x, ac2); ac2 = fmaf(x2.y, y2.y, ac2);
            ac2 = fmaf(x2.z, y2.z, ac2); ac2 = fmaf(x2.w, y2.w, ac2);
            ac3 = fmaf(x3.x, y3.x, ac3); ac3 = fmaf(x3.y, y3.y, ac3);
            ac3 = fmaf(x3.w, y3.w, ac3); ac3 = fmaf(x3.z, y3.z, ac3);
        }
    }
    sRed[quarter * 128 + sub] = (ac0 + ac1) + (ac2 + ac3);
    __syncthreads();

    // ---- epilogue (first 128 threads) ----
    if (tid < 128) {
        float o = sRed[tid] + sRed[128 + tid] + sRed[256 + tid] + sRed[384 + tid]
                + bias[jb + jl];
        if (MODE == 0) {
            o = tanhf(o);
            outp[r * 512 + jb + jl] = o;
        } else if (MODE == 1) {
            float e = __expf(o);                 // |logits0| small: shift-free safe
            g_e0[r * 512 + jb + jl] = e;
            float v = e;
            v += __shfl_down_sync(0xffffffffu, v, 2);
            v += __shfl_down_sync(0xffffffffu, v, 1);
            if ((tid & 3) == 0) g_ps0[r * 128 + bx] = v;
        } else {
            o = tanhf(o);
            outp[r * 512 + jb + jl] = o;
            out_h[((long)r * T + t) * 512 + jb + jl] = o;
            sH[r * 5 + jl] = o;
        }
    }
    if (MODE == 2) {
        __syncthreads();
        if (tid < 128) {
            int hl = tid >> 6, rem = tid & 63;
            int ps = rem & 1, rr = rem >> 1;
            int c0i = jb + ps * 2;
            float v0 = sH[rr * 5 + ps * 2], v1 = sH[rr * 5 + ps * 2 + 1];
            float h0f = bf_hi(v0), h1f = bf_hi(v1);
            uint32_t pk = hl ? pk_bf2(v0 - h0f, v1 - h1f) : pk_bf2(h0f, h1f);
            int ks = c0i >> 4, kk = c0i & 15;
            int hcol = (kk >> 3) & 1, g = (kk >> 1) & 3;
            int lane = (rr & 7) * 4 + g;
            int reg = hcol * 2 + ((rr >> 3) & 1);
            int mtile = rr >> 4;
            ((uint32_t*)g_Af)[(((hl * 32 + ks) * 2 + mtile) * 32 + lane) * 4 + reg] = pk;
        }
    }
}

// ---------------- big GEMM: 197 x 256 threads, double-buffered ks pipeline ----------------
__global__ void __launch_bounds__(256) k_big() {
    cudaGridDependencySynchronize();
    cudaTriggerProgrammaticLaunchCompletion();

    int tid = threadIdx.x, w = tid >> 5, lane = tid & 31;
    int bx = blockIdx.x;
    int n8base = bx * 32 + w * 4;
    float acc[2][4][4];
    #pragma unroll
    for (int m = 0; m < 2; m++)
        #pragma unroll
        for (int n = 0; n < 4; n++)
            #pragma unroll
            for (int rr = 0; rr < 4; rr++) acc[m][n][rr] = 0.f;

    uint4 bv[2][4];
    uint4 ah0[2], ah1[2], al0[2], al1[2];
    #pragma unroll
    for (int n = 0; n < 4; n++)
        bv[0][n] = g_Bf[((long)0 * NB8 + n8base + n) * 32 + lane];
    ah0[0] = g_Af[0 * 32 + lane];
    ah1[0] = g_Af[1 * 32 + lane];
    al0[0] = g_Af[(32 * 2 + 0) * 32 + lane];
    al1[0] = g_Af[(32 * 2 + 1) * 32 + lane];

    #pragma unroll 2
    for (int ks = 0; ks < 32; ks++) {
        int cur = ks & 1, nxt = cur ^ 1;
        if (ks < 31) {
            int kn = ks + 1;
            #pragma unroll
            for (int n = 0; n < 4; n++)
                bv[nxt][n] = g_Bf[((long)kn * NB8 + n8base + n) * 32 + lane];
            ah0[nxt] = g_Af[(kn * 2 + 0) * 32 + lane];
            ah1[nxt] = g_Af[(kn * 2 + 1) * 32 + lane];
            al0[nxt] = g_Af[((32 + kn) * 2 + 0) * 32 + lane];
            al1[nxt] = g_Af[((32 + kn) * 2 + 1) * 32 + lane];
        }
        #pragma unroll
        for (int n = 0; n < 4; n++) {
            mma_bf16(acc[0][n], ah0[cur], bv[cur][n].x, bv[cur][n].y);
            mma_bf16(acc[1][n], ah1[cur], bv[cur][n].x, bv[cur][n].y);
            mma_bf16(acc[0][n], al0[cur], bv[cur][n].x, bv[cur][n].y);
            mma_bf16(acc[1][n], al1[cur], bv[cur][n].x, bv[cur][n].y);
            mma_bf16(acc[0][n], ah0[cur], bv[cur][n].z, bv[cur][n].w);
            mma_bf16(acc[1][n], ah1[cur], bv[cur][n].z, bv[cur][n].w);
        }
    }

    __shared__ float s_sum[8][32];
    __shared__ float s_max[8][32];
    __shared__ int   s_idx[8][32];
    int colw = bx * 256 + w * 32;
    float rsum[4] = {0.f, 0.f, 0.f, 0.f};
    float rmax[4] = {-3e38f, -3e38f, -3e38f, -3e38f};
    int   ridx[4] = {0, 0, 0, 0};

    #pragma unroll
    for (int m = 0; m < 2; m++) {
        #pragma unroll
        for (int n = 0; n < 4; n++) {
            int c0 = colw + n * 8 + ((lane & 3) << 1);
            float bias0 = g_c1p[c0], bias1 = g_c1p[c0 + 1];
            {
                float l0 = acc[m][n][0] + bias0, l1 = acc[m][n][1] + bias1;
                float e0 = __expf(l0), e1 = __expf(l1);
                int row = m * 16 + (lane >> 2);
                *(float2*)&g_E[(long)row * VPAD + c0] = make_float2(e0, e1);
                int slot = m * 2;
                rsum[slot] += e0 + e1;
                if (l0 > rmax[slot] || (l0 == rmax[slot] && c0 < ridx[slot])) { rmax[slot] = l0; ridx[slot] = c0; }
                if (l1 > rmax[slot] || (l1 == rmax[slot] && c0 + 1 < ridx[slot])) { rmax[slot] = l1; ridx[slot] = c0 + 1; }
            }
            {
                float l0 = acc[m][n][2] + bias0, l1 = acc[m][n][3] + bias1;
                float e0 = __expf(l0), e1 = __expf(l1);
                int row = m * 16 + (lane >> 2) + 8;
                *(float2*)&g_E[(long)row * VPAD + c0] = make_float2(e0, e1);
                int slot = m * 2 + 1;
                rsum[slot] += e0 + e1;
                if (l0 > rmax[slot] || (l0 == rmax[slot] && c0 < ridx[slot])) { rmax[slot] = l0; ridx[slot] = c0; }
                if (l1 > rmax[slot] || (l1 == rmax[slot] && c0 + 1 < ridx[slot])) { rmax[slot] = l1; ridx[slot] = c0 + 1; }
            }
        }
    }
    #pragma unroll
    for (int off = 1; off <= 2; off <<= 1) {
        #pragma unroll
        for (int slot = 0; slot < 4; slot++) {
            rsum[slot] += __shfl_xor_sync(0xffffffffu, rsum[slot], off);
            float v = __shfl_xor_sync(0xffffffffu, rmax[slot], off);
            int   i = __shfl_xor_sync(0xffffffffu, ridx[slot], off);
            if (v > rmax[slot] || (v == rmax[slot] && i < ridx[slot])) { rmax[slot] = v; ridx[slot] = i; }
        }
    }
    if ((lane & 3) == 0) {
        #pragma unroll
        for (int slot = 0; slot < 4; slot++) {
            int row = (slot >> 1) * 16 + (lane >> 2) + (slot & 1) * 8;
            s_sum[w][row] = rsum[slot];
            s_max[w][row] = rmax[slot];
            s_idx[w][row] = ridx[slot];
        }
    }
    __syncthreads();
    if (tid < 32) {
        int row = tid;
        float ps = 0.f, pv = -3e38f; int pi = 0;
        #pragma unroll
        for (int ww = 0; ww < 8; ww++) {
            ps += s_sum[ww][row];
            float v = s_max[ww][row]; int i = s_idx[ww][row];
            if (v > pv || (v == pv && i < pi)) { pv = v; pi = i; }
        }
        g_psum[row * NBP + bx] = ps;
        g_pmax[row * NBP + bx] = pv;
        g_pidx[row * NBP + bx] = pi;
    }
}

// ---------------- combine partials: invS + argmax + embed feedback ----------------
__global__ void __launch_bounds__(128) k_comb(const float* __restrict__ emb) {
    cudaGridDependencySynchronize();
    cudaTriggerProgrammaticLaunchCompletion();

    __shared__ float rs[128], rv[128];
    __shared__ int   ri[128];
    int row = blockIdx.x, tid = threadIdx.x;
    float s = 0.f, mv = -3e38f; int mi = 0;
    for (int i = tid; i < NBLK; i += 128) {
        s += g_psum[row * NBP + i];
        float v = g_pmax[row * NBP + i]; int ix = g_pidx[row * NBP + i];
        if (v > mv || (v == mv && ix < mi)) { mv = v; mi = ix; }
    }
    rs[tid] = s; rv[tid] = mv; ri[tid] = mi;
    __syncthreads();
    for (int st = 64; st > 0; st >>= 1) {
        if (tid < st) {
            rs[tid] += rs[tid + st];
            float v = rv[tid + st]; int i = ri[tid + st];
            if (v > rv[tid] || (v == rv[tid] && i < ri[tid])) { rv[tid] = v; ri[tid] = i; }
        }
        __syncthreads();
    }
    if (tid == 0) g_invS[row] = 1.0f / rs[0];
    int am = ri[0];
    for (int j = tid; j < 512; j += 128)
        g_xcur[row * 512 + j] = emb[(long)am * 512 + j];
}

// ---------------- final-step y write ----------------
__global__ void k_writey(float* __restrict__ out_y, int t, int T) {
    int b = blockIdx.y;
    float inv = g_invS[b];
    const float* erow = &g_E[(long)b * VPAD];
    float* yrow = &out_y[((long)b * T + t) * VOCAB];
    for (int j = blockIdx.x * blockDim.x + threadIdx.x; j < VOCAB; j += gridDim.x * blockDim.x)
        yrow[j] = erow[j] * inv;
}

// ---------------- host launcher ----------------
extern "C" void kernel_launch(void* const* d_in, const int* in_sizes, int n_in,
                              void* d_out, int out_size) {
    const int*   x      = (const int*)d_in[0];
    const float* h_prev = (const float*)d_in[3];
    const float* emb    = (const float*)d_in[4];
    const float* U0     = (const float*)d_in[5];
    const float* W0     = (const float*)d_in[6];
    const float* b0     = (const float*)d_in[7];
    const float* V0     = (const float*)d_in[8];
    const float* c0     = (const float*)d_in[9];
    const float* U1     = (const float*)d_in[10];
    const float* W1     = (const float*)d_in[11];
    const float* b1     = (const float*)d_in[12];
    const float* V1     = (const float*)d_in[13];
    const float* c1     = (const float*)d_in[14];

    float* out = (float*)d_out;
    int T = out_size / (BB * (HH + VOCAB));
    float* out_h = out;
    float* out_y = out + (long)BB * T * HH;

    float *p_xcur, *p_h0, *p_h1, *p_Wt;
    cudaGetSymbolAddress((void**)&p_xcur, g_xcur);
    cudaGetSymbolAddress((void**)&p_h0,   g_h0s);
    cudaGetSymbolAddress((void**)&p_h1,   g_h1s);
    cudaGetSymbolAddress((void**)&p_Wt,   g_Wt);
    const float* U0t = p_Wt + 0L * 512 * 512;
    const float* W0t = p_Wt + 1L * 512 * 512;
    const float* V0t = p_Wt + 2L * 512 * 512;
    const float* U1t = p_Wt + 3L * 512 * 512;
    const float* W1t = p_Wt + 4L * 512 * 512;

    const int SMEM_DUAL   = (16512 * 2 + 2064 * 2 + 512 + 160 + 32) * 4;   // 151424
    const int SMEM_SINGLE = (16512 + 2064 + 512 + 160 + 32) * 4;           //  77120
    static bool attr_set = false;
    if (!attr_set) {
        cudaFuncSetAttribute(k_cellx<0>, cudaFuncAttributeMaxDynamicSharedMemorySize, SMEM_DUAL);
        cudaFuncSetAttribute(k_cellx<1>, cudaFuncAttributeMaxDynamicSharedMemorySize, SMEM_SINGLE);
        cudaFuncSetAttribute(k_cellx<2>, cudaFuncAttributeMaxDynamicSharedMemorySize, SMEM_DUAL);
        attr_set = true;
    }

    k_init<<<BB, 512>>>(x, h_prev, emb);
    k_pack_c1<<<(VPAD + 255) / 256, 256>>>(c1);
    k_packw<<<dim3(16, 16, 5), dim3(32, 32)>>>(U0, W0, V0, U1, W1);
    k_pack_b<<<dim3(VPAD / 256, 32), 256>>>(V1);

    // PDL launch config (programmatic stream serialization on the capture stream)
    cudaLaunchAttribute pdlAttr[1];
    pdlAttr[0].id = cudaLaunchAttributeProgrammaticStreamSerialization;
    pdlAttr[0].val.programmaticStreamSerializationAllowed = 1;

    for (int t = 0; t < T; t++) {
        int cur = t & 1;
        float* h0c = p_h0 + cur * BB * HH;
        float* h0n = p_h0 + (cur ^ 1) * BB * HH;
        float* h1c = p_h1 + cur * BB * HH;
        float* h1n = p_h1 + (cur ^ 1) * BB * HH;

        cudaLaunchConfig_t cfg = {};
        cfg.stream = 0;
        cfg.attrs = pdlAttr;
        cfg.numAttrs = 1;

        // cell0: h0 = tanh(x@U0 + h0p@W0 + b0)
        cfg.gridDim = dim3(128); cfg.blockDim = dim3(512); cfg.dynamicSmemBytes = SMEM_DUAL;
        cudaLaunchKernelEx(&cfg, k_cellx<0>,
            (const float*)p_xcur, (const float*)h0c, U0t, W0t, b0,
            (float*)h0n, (float*)nullptr, out_y, t, t - 1, T);

        // head0: [y(t-1) lo half] e0 = exp(h0@V0 + c0) + partials
        cfg.gridDim = dim3(128); cfg.blockDim = dim3(512); cfg.dynamicSmemBytes = SMEM_SINGLE;
        cudaLaunchKernelEx(&cfg, k_cellx<1>,
            (const float*)h0n, (const float*)nullptr, V0t, (const float*)nullptr, c0,
            (float*)nullptr, (float*)nullptr, out_y, t, t - 1, T);

        // cell1: [y(t-1) hi half] inline x1; h1 = tanh(...); out_h + frag pack
        cfg.gridDim = dim3(128); cfg.blockDim = dim3(512); cfg.dynamicSmemBytes = SMEM_DUAL;
        cudaLaunchKernelEx(&cfg, k_cellx<2>,
            (const float*)nullptr, (const float*)h1c, U1t, W1t, b1,
            (float*)h1n, out_h, out_y, t, t - 1, T);

        // big GEMM
        cfg.gridDim = dim3(NBLK); cfg.blockDim = dim3(256); cfg.dynamicSmemBytes = 0;
        cudaLaunchKernelEx(&cfg, k_big);

        // comb
        cfg.gridDim = dim3(BB); cfg.blockDim = dim3(128); cfg.dynamicSmemBytes = 0;
        cudaLaunchKernelEx(&cfg, k_comb, emb);
    }
    // final step's y
    k_writey<<<dim3(64, BB), 256>>>(out_y, T - 1, T);
}